// round 6
// baseline (speedup 1.0000x reference)
#include <cuda_runtime.h>
#include <cstdint>

// ---------------- problem constants ----------------
#define NNODES   20000
#define FEAT     500
#define HID      256
#define LAT      64
#define NPRED    5
#define NCLS     16
#define NODE_LEN (NNODES + NNODES * NPRED)      // 120000
#define GENF     (NPRED * FEAT)                 // 2500
#define FC1N     256
#define FC2N     2048

#define OUT_GEN_OFF ((long long)NNODES)
#define OUT_NC_OFF  ((long long)NNODES + (long long)NNODES * GENF)

// ---------------- scratch (static device globals; no allocation) ------------
__device__ float g_bufA[(size_t)NODE_LEN * HID];
__device__ float g_bufB[(size_t)NODE_LEN * HID];
__device__ float g_z[(size_t)NNODES * LAT];
__device__ float g_zn[(size_t)NNODES * LAT];
__device__ float g_g1[(size_t)NNODES * FC1N];
__device__ float g_g2[(size_t)NNODES * FC2N];
__device__ float g_c7[(size_t)NODE_LEN * NCLS];
__device__ float g_acc16[(size_t)NODE_LEN * NCLS];
__device__ float g_rowsum[NODE_LEN];
__device__ int   g_pdeg[NNODES];
__device__ int   g_is64;
// transposed (tf32-rounded) weights, K-major [Npad, Kpad]
__device__ float g_wt_fc2[(size_t)2048 * 256];
__device__ float g_wt_flat[(size_t)2560 * 2048];
__device__ float g_wt_gc3[(size_t)256 * 512];

// ---------------- helpers ----------------
__device__ __forceinline__ uint32_t smem_u32(const void* p) {
    uint32_t a;
    asm("{ .reg .u64 t; cvta.to.shared.u64 t, %1; cvt.u32.u64 %0, t; }" : "=r"(a) : "l"(p));
    return a;
}
__device__ __forceinline__ float to_tf32(float f) {
    uint32_t r;
    asm("cvt.rna.tf32.f32 %0, %1;" : "=r"(r) : "f"(f));
    return __uint_as_float(r);
}
__device__ __forceinline__ void ldsm_x4(uint32_t addr, uint32_t* r) {
    asm volatile("ldmatrix.sync.aligned.m8n8.x4.shared.b16 {%0,%1,%2,%3}, [%4];"
                 : "=r"(r[0]), "=r"(r[1]), "=r"(r[2]), "=r"(r[3]) : "r"(addr));
}
__device__ __forceinline__ void mma_tf32(float* c, const uint32_t* a, uint32_t b0, uint32_t b1) {
    asm volatile(
        "mma.sync.aligned.m16n8k8.row.col.f32.tf32.tf32.f32 "
        "{%0,%1,%2,%3}, {%4,%5,%6,%7}, {%8,%9}, {%0,%1,%2,%3};"
        : "+f"(c[0]), "+f"(c[1]), "+f"(c[2]), "+f"(c[3])
        : "r"(a[0]), "r"(a[1]), "r"(a[2]), "r"(a[3]), "r"(b0), "r"(b1));
}
// vector reduction: one instruction, 16 bytes (sm_90+)
__device__ __forceinline__ void red_add_v4(float* addr, float4 v) {
    asm volatile("red.global.v4.f32.add [%0], {%1, %2, %3, %4};"
                 :: "l"(addr), "f"(v.x), "f"(v.y), "f"(v.z), "f"(v.w) : "memory");
}
#define CP_ASYNC16(dst, src) \
    asm volatile("cp.async.cg.shared.global [%0], [%1], 16;" :: "r"(dst), "l"(src))
#define CP_ASYNC16Z(dst, src, bytes) \
    asm volatile("cp.async.cg.shared.global [%0], [%1], 16, %2;" :: "r"(dst), "l"(src), "r"(bytes))
#define CP_COMMIT() asm volatile("cp.async.commit_group;" ::: "memory")
#define CP_WAIT(n)  asm volatile("cp.async.wait_group %0;" :: "n"(n) : "memory")

// ---------------- index dtype detection ----------------
__global__ void detect_idx_kernel(const void* adj_rows) {
    int lane = threadIdx.x;
    const long long* p = (const long long*)adj_rows;
    int bad = 0;
    for (int i = lane; i < 256; i += 32) {
        long long v = p[i];
        if (v < 0 || v >= NODE_LEN) bad = 1;
    }
    unsigned m = __ballot_sync(0xffffffffu, bad);
    if (lane == 0) g_is64 = (m == 0) ? 1 : 0;
}
__device__ __forceinline__ long long load_idx(const void* p, long long i) {
    return g_is64 ? ((const long long*)p)[i] : (long long)((const int*)p)[i];
}

// ---------------- weight transpose + tf32 round: W[K,N] -> WT[Npad,Kpad] ----
__global__ void transpose_tf32_kernel(const float* __restrict__ W, float* __restrict__ WT,
                                      int K, int N, int Kpad, int Npad) {
    __shared__ float tile[32][33];
    int kb = blockIdx.x * 32, nb = blockIdx.y * 32;
    int tx = threadIdx.x, ty = threadIdx.y;   // 32 x 8
#pragma unroll
    for (int i = 0; i < 4; i++) {
        int k = kb + ty + i * 8, n = nb + tx;
        tile[ty + i * 8][tx] = (k < K && n < N) ? W[(long long)k * N + n] : 0.0f;
    }
    __syncthreads();
#pragma unroll
    for (int i = 0; i < 4; i++) {
        int n = nb + ty + i * 8, k = kb + tx;
        if (n < Npad && k < Kpad)
            WT[(long long)n * Kpad + k] = to_tf32(tile[tx][ty + i * 8]);
    }
}

// ---------------- tf32 mma.sync GEMM: C[M,N] = A[M,K] @ W[K,N] --------------
#define GSTAGES 4
#define G_STRIDE_F 36
#define G_MAT_BYTES (128 * G_STRIDE_F * 4)          // 18432
#define G_STAGE_BYTES (2 * G_MAT_BYTES)             // 36864
#define G_SMEM_TOTAL (GSTAGES * G_STAGE_BYTES)      // 147456

template <int EPI, bool SPLIT>
__global__ void __launch_bounds__(256, 1) mma_gemm_kernel(
    const float* __restrict__ A, const float* __restrict__ Agen, int splitRows,
    const float* __restrict__ BT, const float* __restrict__ bias,
    float* __restrict__ C, int M, int N, int K, int Kpad)
{
    extern __shared__ char smem[];
    const uint32_t sbase = smem_u32(smem);
    const int tid = threadIdx.x;
    const int wid = tid >> 5, lane = tid & 31;
    const int gid = lane >> 2, tig = lane & 3;
    const int warp_m = wid & 3, warp_n = wid >> 2;
    const int m0 = blockIdx.y * 128, n0 = blockIdx.x * 128;

    const int crow = tid >> 1;
    const int cboff = (tid & 1) * 64;

    const float* aptr;
    {
        int r = m0 + crow;
        int rr = (r < M) ? r : (M - 1);
        if (!SPLIT || rr < splitRows) {
            aptr = A + (long long)rr * K;
        } else {
            int q = rr - splitRows;
            aptr = Agen + (long long)(q / NPRED) * GENF + (long long)(q % NPRED) * FEAT;
        }
    }
    const float* bptr = BT + (long long)(n0 + crow) * Kpad;

    const uint32_t sA_wr = sbase + (uint32_t)crow * 144u + (uint32_t)cboff;
    const uint32_t sB_wr = sA_wr + G_MAT_BYTES;

    const int nChunks = (K + 31) >> 5;

    auto issue = [&](int chunk) {
        int s = chunk & (GSTAGES - 1);
        int k0 = chunk << 5;
        uint32_t da = sA_wr + (uint32_t)s * G_STAGE_BYTES;
        uint32_t db = sB_wr + (uint32_t)s * G_STAGE_BYTES;
        const char* ga = (const char*)(aptr + k0) + cboff;
        const char* gb = (const char*)(bptr + k0) + cboff;
        int avail = K * 4 - (k0 * 4 + cboff);
        if (avail >= 64) {
#pragma unroll
            for (int i = 0; i < 4; i++) CP_ASYNC16(da + i * 16, ga + i * 16);
        } else {
#pragma unroll
            for (int i = 0; i < 4; i++) {
                int b = avail - i * 16;
                int bytes = b >= 16 ? 16 : (b > 0 ? b : 0);
                const char* src = (bytes > 0) ? (ga + i * 16) : (const char*)aptr;
                CP_ASYNC16Z(da + i * 16, src, bytes);
            }
        }
#pragma unroll
        for (int i = 0; i < 4; i++) CP_ASYNC16(db + i * 16, gb + i * 16);
        CP_COMMIT();
    };

    float acc[2][8][4];
#pragma unroll
    for (int f = 0; f < 2; f++)
#pragma unroll
        for (int j = 0; j < 8; j++)
#pragma unroll
            for (int q = 0; q < 4; q++) acc[f][j][q] = 0.0f;

    int pro = (GSTAGES - 1 < nChunks) ? GSTAGES - 1 : nChunks;
    for (int s = 0; s < pro; s++) issue(s);
    for (int s = pro; s < GSTAGES - 1; s++) CP_COMMIT();

    // ldmatrix per-thread source offsets (bytes, relative to stage base)
    // A frag f (16x8): threads 0-7 -> mat0 rows (m..m+7, k0-3); 8-15 -> mat1 (m+8.., k0-3);
    //                  16-23 -> mat2 (m.., k4-7); 24-31 -> mat3 (m+8.., k4-7)
    uint32_t a_off[2];
#pragma unroll
    for (int f = 0; f < 2; f++) {
        uint32_t row = (uint32_t)(warp_m * 32 + f * 16 + (lane & 15));
        uint32_t colb = (uint32_t)((lane >> 4) << 4);          // 0 or 16 (k+4 group)
        a_off[f] = row * 144u + colb;
    }
    // B frag pair jp (n-rows jp*16..+15): threads 0-7 -> mat0 (n..n+7, k0-3);
    //   8-15 -> mat1 (n..n+7, k4-7); 16-23 -> mat2 (n+8.., k0-3); 24-31 -> mat3 (n+8.., k4-7)
    uint32_t b_off[4];
#pragma unroll
    for (int jp = 0; jp < 4; jp++) {
        uint32_t row = (uint32_t)(warp_n * 64 + jp * 16 + ((lane >> 4) << 3) + (lane & 7));
        uint32_t colb = (uint32_t)(((lane >> 3) & 1) << 4);    // 0 or 16
        b_off[jp] = row * 144u + colb;
    }

    for (int i = 0; i < nChunks; i++) {
        if (i + GSTAGES - 1 < nChunks) issue(i + GSTAGES - 1);
        else CP_COMMIT();
        CP_WAIT(GSTAGES - 1);
        __syncthreads();

        uint32_t sA = sbase + (uint32_t)(i & (GSTAGES - 1)) * G_STAGE_BYTES;
        uint32_t sB = sA + G_MAT_BYTES;
#pragma unroll
        for (int kk = 0; kk < 32; kk += 8) {
            uint32_t afr[2][4];
            ldsm_x4(sA + a_off[0] + kk * 4, afr[0]);
            ldsm_x4(sA + a_off[1] + kk * 4, afr[1]);
#pragma unroll
            for (int jp = 0; jp < 4; jp++) {
                uint32_t br[4];
                ldsm_x4(sB + b_off[jp] + kk * 4, br);
                mma_tf32(acc[0][2 * jp + 0], afr[0], br[0], br[1]);
                mma_tf32(acc[1][2 * jp + 0], afr[1], br[0], br[1]);
                mma_tf32(acc[0][2 * jp + 1], afr[0], br[2], br[3]);
                mma_tf32(acc[1][2 * jp + 1], afr[1], br[2], br[3]);
            }
        }
        __syncthreads();
    }

#pragma unroll
    for (int f = 0; f < 2; f++) {
        int r0 = m0 + warp_m * 32 + f * 16 + gid;
#pragma unroll
        for (int j = 0; j < 8; j++) {
            int c = n0 + warp_n * 64 + j * 8 + tig * 2;
            if (c >= N) continue;
            float v0 = acc[f][j][0], v1 = acc[f][j][1];
            float v2 = acc[f][j][2], v3 = acc[f][j][3];
            if (EPI >= 1) {
                float bb0 = bias[c], bb1 = bias[c + 1];
                v0 += bb0; v1 += bb1; v2 += bb0; v3 += bb1;
            }
            if (EPI == 1) {
                v0 = fmaxf(v0, 0.f); v1 = fmaxf(v1, 0.f);
                v2 = fmaxf(v2, 0.f); v3 = fmaxf(v3, 0.f);
            }
            if (EPI == 2) {
                v0 = tanhf(v0); v1 = tanhf(v1);
                v2 = tanhf(v2); v3 = tanhf(v3);
            }
            if (r0 < M)     *(float2*)(C + (long long)r0 * N + c)       = make_float2(v0, v1);
            if (r0 + 8 < M) *(float2*)(C + (long long)(r0 + 8) * N + c) = make_float2(v2, v3);
        }
    }
}

// ---------------- SIMT SGEMM (precision-critical / small GEMMs) ----
#define BM 128
#define BN 128
#define BK 8
template <int EPI>
__global__ void __launch_bounds__(256, 2) sgemm_kernel(
    const float* __restrict__ A, const float* __restrict__ B,
    const float* __restrict__ bias, float* __restrict__ C, int M, int N, int K)
{
    __shared__ float As[BK][BM];
    __shared__ float Bs[BK][BN];
    const int tid = threadIdx.x;
    const int tx = tid & 15, ty = tid >> 4;
    const int rbase = blockIdx.y * BM, cbase = blockIdx.x * BN;
    float acc[8][8];
#pragma unroll
    for (int i = 0; i < 8; i++)
#pragma unroll
        for (int j = 0; j < 8; j++) acc[i][j] = 0.0f;
    const int arow = tid >> 1, acol = (tid & 1) * 4;
    const int brow = tid >> 5, bcol = (tid & 31) * 4;
    const float* arowptr = (rbase + arow < M) ? A + (long long)(rbase + arow) * K : nullptr;

    for (int kt = 0; kt < K; kt += BK) {
        float4 av = make_float4(0.f, 0.f, 0.f, 0.f);
        if (arowptr) {
            int kc = kt + acol;
            if (kc + 3 < K) av = *(const float4*)(arowptr + kc);
            else {
                if (kc + 0 < K) av.x = arowptr[kc + 0];
                if (kc + 1 < K) av.y = arowptr[kc + 1];
                if (kc + 2 < K) av.z = arowptr[kc + 2];
                if (kc + 3 < K) av.w = arowptr[kc + 3];
            }
        }
        As[acol + 0][arow] = av.x; As[acol + 1][arow] = av.y;
        As[acol + 2][arow] = av.z; As[acol + 3][arow] = av.w;
        float4 bv = make_float4(0.f, 0.f, 0.f, 0.f);
        {
            int kr = kt + brow, cc = cbase + bcol;
            if (kr < K) {
                const float* bp = B + (long long)kr * N + cc;
                if (cc + 3 < N) bv = *(const float4*)bp;
                else {
                    if (cc + 0 < N) bv.x = bp[0];
                    if (cc + 1 < N) bv.y = bp[1];
                    if (cc + 2 < N) bv.z = bp[2];
                    if (cc + 3 < N) bv.w = bp[3];
                }
            }
        }
        *(float4*)&Bs[brow][bcol] = bv;
        __syncthreads();
#pragma unroll
        for (int k = 0; k < BK; k++) {
            float ra[8], rb[8];
            *(float4*)&ra[0] = *(const float4*)&As[k][ty * 4];
            *(float4*)&ra[4] = *(const float4*)&As[k][64 + ty * 4];
            *(float4*)&rb[0] = *(const float4*)&Bs[k][tx * 4];
            *(float4*)&rb[4] = *(const float4*)&Bs[k][64 + tx * 4];
#pragma unroll
            for (int i = 0; i < 8; i++)
#pragma unroll
                for (int j = 0; j < 8; j++) acc[i][j] += ra[i] * rb[j];
        }
        __syncthreads();
    }
#pragma unroll
    for (int i = 0; i < 8; i++) {
        int r = rbase + ((i < 4) ? (ty * 4 + i) : (64 + ty * 4 + i - 4));
        if (r >= M) continue;
#pragma unroll
        for (int j = 0; j < 8; j++) {
            int c = cbase + ((j < 4) ? (tx * 4 + j) : (64 + tx * 4 + j - 4));
            if (c >= N) continue;
            float v = acc[i][j];
            if (EPI >= 1) v += bias[c];
            if (EPI == 1) v = fmaxf(v, 0.0f);
            C[(long long)r * N + c] = v;
        }
    }
}

// ---------------- skinny GEMM for gc4 ----------------
__global__ void skinny16_kernel(const float* __restrict__ X, const float* __restrict__ W,
                                float* __restrict__ C, int M)
{
    __shared__ float Ws[256 * 16];
    int tid = threadIdx.x;   // 128
    for (int i = tid; i < 256 * 16; i += 128) Ws[i] = W[i];
    __syncthreads();
    int r = blockIdx.x * 128 + tid;
    if (r >= M) return;
    const float* x = X + (long long)r * 256;
    float acc[16];
#pragma unroll
    for (int q = 0; q < 16; q++) acc[q] = 0.0f;
    for (int k = 0; k < 256; k += 4) {
        float4 a = *(const float4*)(x + k);
#pragma unroll
        for (int q = 0; q < 16; q++)
            acc[q] += a.x * Ws[(k + 0) * 16 + q] + a.y * Ws[(k + 1) * 16 + q]
                    + a.z * Ws[(k + 2) * 16 + q] + a.w * Ws[(k + 3) * 16 + q];
    }
    float* co = C + (long long)r * 16;
#pragma unroll
    for (int q = 0; q < 16; q += 4)
        *(float4*)(co + q) = make_float4(acc[q], acc[q + 1], acc[q + 2], acc[q + 3]);
}

// ---------------- SpMM via vector-reduction scatter ----------------
__global__ void spmm_scatter_kernel(const void* __restrict__ rows, const void* __restrict__ cols,
                                    const float* __restrict__ vals, const float* __restrict__ x,
                                    float* __restrict__ acc, long long nnz, int D, int shift)
{
    long long idx = (long long)blockIdx.x * blockDim.x + threadIdx.x;
    int mask = (1 << shift) - 1;
    int d4 = (int)(idx & mask);
    long long e = idx >> shift;
    if (e >= nnz) return;
    long long r = load_idx(rows, e);
    long long c = load_idx(cols, e);
    float v = vals[e];
    float4 xv = *(const float4*)(x + c * D + 4 * d4);
    red_add_v4(acc + r * D + 4 * d4,
               make_float4(v * xv.x, v * xv.y, v * xv.z, v * xv.w));
}

__global__ void bias_relu_kernel(float* __restrict__ y, const float* __restrict__ acc,
                                 const float* __restrict__ bias, long long total, int Dmask)
{
    long long i = (long long)blockIdx.x * blockDim.x + threadIdx.x;
    if (i >= total) return;
    y[i] = fmaxf(acc[i] + bias[i & Dmask], 0.0f);
}

__global__ void degree_kernel(const float* __restrict__ z, const float* __restrict__ Wr,
                              const float* __restrict__ br, float* __restrict__ deg_out,
                              int* __restrict__ pdeg, int n)
{
    int r = blockIdx.x * (blockDim.x >> 5) + (threadIdx.x >> 5);
    int lane = threadIdx.x & 31;
    if (r >= n) return;
    float s = z[(long long)r * LAT + lane] * Wr[lane]
            + z[(long long)r * LAT + 32 + lane] * Wr[32 + lane];
#pragma unroll
    for (int o = 16; o; o >>= 1) s += __shfl_xor_sync(0xffffffffu, s, o);
    if (lane == 0) {
        float d = fmaxf(s + br[0], 0.0f);
        deg_out[r] = d;
        int pi = (int)d;
        if (pi > NPRED) pi = NPRED;
        pdeg[r] = pi;
    }
}

__global__ void add_kernel(float* __restrict__ o, const float* __restrict__ a,
                           const float* __restrict__ b, long long n)
{
    long long i = (long long)blockIdx.x * blockDim.x + threadIdx.x;
    if (i < n) o[i] = a[i] + b[i];
}

// ---------------- mend graph ----------------
__global__ void rowsum_init_kernel(float* __restrict__ rowsum, const int* __restrict__ pdeg)
{
    int i = blockIdx.x * blockDim.x + threadIdx.x;
    if (i >= NODE_LEN) return;
    if (i < NNODES) {
        rowsum[i] = 1.0f + (float)pdeg[i];
    } else {
        int rr = i - NNODES;
        int node = rr / NPRED, j = rr % NPRED;
        rowsum[i] = 1.0f + ((j < pdeg[node]) ? 1.0f : 0.0f);
    }
}

__global__ void rowsum_edges_kernel(const void* __restrict__ edges, float* __restrict__ rowsum, int E)
{
    int e = blockIdx.x * blockDim.x + threadIdx.x;
    if (e >= E) return;
    long long lo = load_idx(edges, 2LL * e);
    long long hi = load_idx(edges, 2LL * e + 1);
    atomicAdd(&rowsum[lo], 1.0f);
    atomicAdd(&rowsum[hi], 1.0f);
}

__global__ void mend_orig_scatter_kernel(const void* __restrict__ edges,
                                         const float* __restrict__ x,
                                         float* __restrict__ acc, int E, int D, int shift)
{
    long long idx = (long long)blockIdx.x * blockDim.x + threadIdx.x;
    int mask = (1 << shift) - 1;
    int d4 = (int)(idx & mask);
    long long e = idx >> shift;
    if (e >= E) return;
    long long lo = load_idx(edges, 2 * e);
    long long hi = load_idx(edges, 2 * e + 1);
    float4 xh = *(const float4*)(x + hi * D + 4 * d4);
    float4 xl = *(const float4*)(x + lo * D + 4 * d4);
    red_add_v4(acc + lo * D + 4 * d4, xh);
    red_add_v4(acc + hi * D + 4 * d4, xl);
}

__global__ void mend_new_scatter_kernel(const float* __restrict__ x, float* __restrict__ acc,
                                        const int* __restrict__ pdeg, int D, int shift)
{
    long long idx = (long long)blockIdx.x * blockDim.x + threadIdx.x;
    int mask = (1 << shift) - 1;
    int d4 = (int)(idx & mask);
    long long t = idx >> shift;
    if (t >= (long long)NNODES * NPRED) return;
    int node = (int)(t / NPRED);
    int j = (int)(t - (long long)node * NPRED);
    if (j < pdeg[node]) {
        long long gcol = NNODES + t;
        float4 xg = *(const float4*)(x + gcol * D + 4 * d4);
        red_add_v4(acc + (long long)node * D + 4 * d4, xg);
        float4 xn = *(const float4*)(x + (long long)node * D + 4 * d4);
        *(float4*)(acc + gcol * D + 4 * d4) = xn;
    }
}

__global__ void mend_finalize_kernel(float* __restrict__ y, const float* __restrict__ acc,
                                     const float* __restrict__ x, const float* __restrict__ rowsum,
                                     const float* __restrict__ bias, long long total,
                                     int Dmask, int shiftD)
{
    long long i = (long long)blockIdx.x * blockDim.x + threadIdx.x;
    if (i >= total) return;
    long long r = i >> shiftD;
    int d = (int)(i & Dmask);
    float v = (acc[i] + x[i]) / rowsum[r] + bias[d];
    y[i] = fmaxf(v, 0.0f);
}

// ---------------- host ----------------
static inline int cdiv(long long a, long long b) { return (int)((a + b - 1) / b); }

extern "C" void kernel_launch(void* const* d_in, const int* in_sizes, int n_in,
                              void* d_out, int out_size)
{
    const float* feat     = (const float*)d_in[0];
    const void*  edges    = d_in[1];
    const void*  adj_rows = d_in[2];
    const void*  adj_cols = d_in[3];
    const float* adj_vals = (const float*)d_in[4];
    const float* noise    = (const float*)d_in[5];
    const float* W_gc1 = (const float*)d_in[6];   const float* b_gc1 = (const float*)d_in[7];
    const float* W_gc2 = (const float*)d_in[8];   const float* b_gc2 = (const float*)d_in[9];
    const float* W_reg = (const float*)d_in[10];  const float* b_reg = (const float*)d_in[11];
    const float* W_fc1 = (const float*)d_in[12];  const float* b_fc1 = (const float*)d_in[13];
    const float* W_fc2 = (const float*)d_in[14];  const float* b_fc2 = (const float*)d_in[15];
    const float* W_flat = (const float*)d_in[16]; const float* b_flat = (const float*)d_in[17];
    const float* W_gc3 = (const float*)d_in[18];  const float* b_gc3 = (const float*)d_in[19];
    const float* W_gc4 = (const float*)d_in[20];  const float* b_gc4 = (const float*)d_in[21];

    float* out = (float*)d_out;
    float* out_deg = out;
    float* out_gen = out + OUT_GEN_OFF;
    float* out_nc  = out + OUT_NC_OFF;

    const long long nnz_adj = in_sizes[2];
    const int E = in_sizes[1] / 2;

    void* p;
    float *bufA, *bufB, *z, *zn, *g1, *g2, *c7, *acc16, *rowsum;
    float *wt_fc2, *wt_flat, *wt_gc3;
    int *pdeg;
    cudaGetSymbolAddress(&p, g_bufA);  bufA  = (float*)p;
    cudaGetSymbolAddress(&p, g_bufB);  bufB  = (float*)p;
    cudaGetSymbolAddress(&p, g_z);     z     = (float*)p;
    cudaGetSymbolAddress(&p, g_zn);    zn    = (float*)p;
    cudaGetSymbolAddress(&p, g_g1);    g1    = (float*)p;
    cudaGetSymbolAddress(&p, g_g2);    g2    = (float*)p;
    cudaGetSymbolAddress(&p, g_c7);    c7    = (float*)p;
    cudaGetSymbolAddress(&p, g_acc16); acc16 = (float*)p;
    cudaGetSymbolAddress(&p, g_rowsum); rowsum = (float*)p;
    cudaGetSymbolAddress(&p, g_pdeg);  pdeg  = (int*)p;
    cudaGetSymbolAddress(&p, g_wt_fc2);  wt_fc2  = (float*)p;
    cudaGetSymbolAddress(&p, g_wt_flat); wt_flat = (float*)p;
    cudaGetSymbolAddress(&p, g_wt_gc3);  wt_gc3  = (float*)p;

    cudaFuncSetAttribute((const void*)mma_gemm_kernel<1, false>,
                         cudaFuncAttributeMaxDynamicSharedMemorySize, G_SMEM_TOTAL);
    cudaFuncSetAttribute((const void*)mma_gemm_kernel<2, false>,
                         cudaFuncAttributeMaxDynamicSharedMemorySize, G_SMEM_TOTAL);
    cudaFuncSetAttribute((const void*)mma_gemm_kernel<0, true>,
                         cudaFuncAttributeMaxDynamicSharedMemorySize, G_SMEM_TOTAL);

    const int TB = 256;
    dim3 tblk(32, 8);

    // 0) index-width detection + weight transposes (tf32-rounded, K-major)
    detect_idx_kernel<<<1, 32>>>(adj_rows);
    transpose_tf32_kernel<<<dim3(cdiv(256, 32), cdiv(2048, 32)), tblk>>>(W_fc2, wt_fc2, 256, 2048, 256, 2048);
    transpose_tf32_kernel<<<dim3(cdiv(2048, 32), cdiv(2560, 32)), tblk>>>(W_flat, wt_flat, 2048, 2500, 2048, 2560);
    transpose_tf32_kernel<<<dim3(cdiv(512, 32), cdiv(256, 32)), tblk>>>(W_gc3, wt_gc3, 500, 256, 512, 256);

    // 1) XW1 = feat @ W_gc1 (fp32 exact — feeds the int(degree) cliff)
    {
        dim3 grid(cdiv(HID, BN), cdiv(NNODES, BM));
        sgemm_kernel<0><<<grid, TB>>>(feat, W_gc1, nullptr, bufA, NNODES, HID, FEAT);
    }
    // 2) h = relu(spmm + b1)
    cudaMemsetAsync(bufB, 0, (size_t)NNODES * HID * sizeof(float));
    spmm_scatter_kernel<<<cdiv(nnz_adj << 6, TB), TB>>>(adj_rows, adj_cols, adj_vals,
                                                        bufA, bufB, nnz_adj, HID, 6);
    bias_relu_kernel<<<cdiv((long long)NNODES * HID, TB), TB>>>(bufB, bufB, b_gc1,
                                                                (long long)NNODES * HID, HID - 1);
    // 3) hW2 = h @ W_gc2
    {
        dim3 grid(cdiv(LAT, BN), cdiv(NNODES, BM));
        sgemm_kernel<0><<<grid, TB>>>(bufB, W_gc2, nullptr, bufA, NNODES, LAT, HID);
    }
    // 4) z = relu(spmm + b2)
    cudaMemsetAsync(bufB, 0, (size_t)NNODES * LAT * sizeof(float));
    spmm_scatter_kernel<<<cdiv(nnz_adj << 4, TB), TB>>>(adj_rows, adj_cols, adj_vals,
                                                        bufA, bufB, nnz_adj, LAT, 4);
    bias_relu_kernel<<<cdiv((long long)NNODES * LAT, TB), TB>>>(z, bufB, b_gc2,
                                                                (long long)NNODES * LAT, LAT - 1);
    // 5) degree + pred_deg
    degree_kernel<<<cdiv(NNODES, TB / 32), TB>>>(z, W_reg, b_reg, out_deg, pdeg, NNODES);
    // 6) zn = z + noise
    add_kernel<<<cdiv((long long)NNODES * LAT, TB), TB>>>(zn, z, noise, (long long)NNODES * LAT);
    // 7) g1 = relu(zn @ W_fc1 + b) — small K, SIMT
    {
        dim3 grid(cdiv(FC1N, BN), cdiv(NNODES, BM));
        sgemm_kernel<1><<<grid, TB>>>(zn, W_fc1, b_fc1, g1, NNODES, FC1N, LAT);
    }
    // 8) g2 = relu(g1 @ W_fc2 + b) — tf32 mma
    {
        dim3 grid(FC2N / 128, cdiv(NNODES, 128));
        mma_gemm_kernel<1, false><<<grid, 256, G_SMEM_TOTAL>>>(
            g1, nullptr, 0, wt_fc2, b_fc2, g2, NNODES, FC2N, FC1N, 256);
    }
    // 9) gen_feat = tanh(g2 @ W_flat + b) — tf32 mma
    {
        dim3 grid(2560 / 128, cdiv(NNODES, 128));
        mma_gemm_kernel<2, false><<<grid, 256, G_SMEM_TOTAL>>>(
            g2, nullptr, 0, wt_flat, b_flat, out_gen, NNODES, GENF, FC2N, 2048);
    }
    // 10) fillW3 = fill_feats @ W_gc3 — tf32 mma with row indirection
    {
        dim3 grid(HID / 128, cdiv(NODE_LEN, 128));
        mma_gemm_kernel<0, true><<<grid, 256, G_SMEM_TOTAL>>>(
            feat, out_gen, NNODES, wt_gc3, nullptr, bufA, NODE_LEN, HID, FEAT, 512);
    }
    // 11) mend rowsum
    rowsum_init_kernel<<<cdiv(NODE_LEN, TB), TB>>>(rowsum, pdeg);
    rowsum_edges_kernel<<<cdiv(E, TB), TB>>>(edges, rowsum, E);
    // 12) mend spmm layer 1
    cudaMemsetAsync(bufB, 0, (size_t)NODE_LEN * HID * sizeof(float));
    mend_orig_scatter_kernel<<<cdiv((long long)E << 6, TB), TB>>>(edges, bufA, bufB, E, HID, 6);
    mend_new_scatter_kernel<<<cdiv(((long long)NNODES * NPRED) << 6, TB), TB>>>(bufA, bufB, pdeg, HID, 6);
    mend_finalize_kernel<<<cdiv((long long)NODE_LEN * HID, TB), TB>>>(
        bufB, bufB, bufA, rowsum, b_gc3, (long long)NODE_LEN * HID, HID - 1, 8);
    // 13) c7 = h2 @ W_gc4 — skinny N=16
    skinny16_kernel<<<cdiv(NODE_LEN, 128), 128>>>(bufB, W_gc4, c7, NODE_LEN);
    // 14) mend spmm layer 2
    cudaMemsetAsync(acc16, 0, (size_t)NODE_LEN * NCLS * sizeof(float));
    mend_orig_scatter_kernel<<<cdiv((long long)E << 2, TB), TB>>>(edges, c7, acc16, E, NCLS, 2);
    mend_new_scatter_kernel<<<cdiv(((long long)NNODES * NPRED) << 2, TB), TB>>>(c7, acc16, pdeg, NCLS, 2);
    mend_finalize_kernel<<<cdiv((long long)NODE_LEN * NCLS, TB), TB>>>(
        out_nc, acc16, c7, rowsum, b_gc4, (long long)NODE_LEN * NCLS, NCLS - 1, 4);

    (void)n_in; (void)out_size;
}

// round 8
// speedup vs baseline: 1.0258x; 1.0258x over previous
#include <cuda_runtime.h>
#include <cstdint>

// ---------------- problem constants ----------------
#define NNODES   20000
#define FEAT     500
#define HID      256
#define LAT      64
#define NPRED    5
#define NCLS     16
#define NODE_LEN (NNODES + NNODES * NPRED)      // 120000
#define GENF     (NPRED * FEAT)                 // 2500
#define FC1N     256
#define FC2N     2048

#define OUT_GEN_OFF ((long long)NNODES)
#define OUT_NC_OFF  ((long long)NNODES + (long long)NNODES * GENF)

// ---------------- scratch (static device globals; no allocation) ------------
__device__ float g_bufA[(size_t)NODE_LEN * HID];
__device__ float g_bufB[(size_t)NODE_LEN * HID];
__device__ float g_z[(size_t)NNODES * LAT];
__device__ float g_zn[(size_t)NNODES * LAT];
__device__ float g_g1[(size_t)NNODES * FC1N];
__device__ float g_g2[(size_t)NNODES * FC2N];
__device__ float g_c7[(size_t)NODE_LEN * NCLS];
__device__ float g_rowscr[NODE_LEN];
__device__ int   g_pdeg[NNODES];
__device__ int   g_is64;
// transposed (tf32-rounded) weights, K-major [Npad, Kpad]
__device__ float g_wt_fc2[(size_t)2048 * 256];
__device__ float g_wt_flat[(size_t)2560 * 2048];
__device__ float g_wt_gc3[(size_t)256 * 512];
// CSR scratch
__device__ int   g_cnt[NODE_LEN];
__device__ int   g_fill[NODE_LEN];
__device__ int   g_off_enc[NNODES + 1];
__device__ int   g_off_mend[NODE_LEN + 1];
__device__ int   g_ecol[700000];
__device__ float g_eval[700000];
__device__ int   g_mcol[900000];

// ---------------- helpers ----------------
__device__ __forceinline__ uint32_t smem_u32(const void* p) {
    uint32_t a;
    asm("{ .reg .u64 t; cvta.to.shared.u64 t, %1; cvt.u32.u64 %0, t; }" : "=r"(a) : "l"(p));
    return a;
}
__device__ __forceinline__ float to_tf32(float f) {
    uint32_t r;
    asm("cvt.rna.tf32.f32 %0, %1;" : "=r"(r) : "f"(f));
    return __uint_as_float(r);
}
__device__ __forceinline__ void ldsm_x4(uint32_t addr, uint32_t* r) {
    asm volatile("ldmatrix.sync.aligned.m8n8.x4.shared.b16 {%0,%1,%2,%3}, [%4];"
                 : "=r"(r[0]), "=r"(r[1]), "=r"(r[2]), "=r"(r[3]) : "r"(addr));
}
__device__ __forceinline__ void mma_tf32(float* c, const uint32_t* a, uint32_t b0, uint32_t b1) {
    asm volatile(
        "mma.sync.aligned.m16n8k8.row.col.f32.tf32.tf32.f32 "
        "{%0,%1,%2,%3}, {%4,%5,%6,%7}, {%8,%9}, {%0,%1,%2,%3};"
        : "+f"(c[0]), "+f"(c[1]), "+f"(c[2]), "+f"(c[3])
        : "r"(a[0]), "r"(a[1]), "r"(a[2]), "r"(a[3]), "r"(b0), "r"(b1));
}
#define CP_ASYNC16(dst, src) \
    asm volatile("cp.async.cg.shared.global [%0], [%1], 16;" :: "r"(dst), "l"(src))
#define CP_ASYNC16Z(dst, src, bytes) \
    asm volatile("cp.async.cg.shared.global [%0], [%1], 16, %2;" :: "r"(dst), "l"(src), "r"(bytes))
#define CP_COMMIT() asm volatile("cp.async.commit_group;" ::: "memory")
#define CP_WAIT(n)  asm volatile("cp.async.wait_group %0;" :: "n"(n) : "memory")

// ---------------- index dtype detection ----------------
__global__ void detect_idx_kernel(const void* adj_rows) {
    int lane = threadIdx.x;
    const long long* p = (const long long*)adj_rows;
    int bad = 0;
    for (int i = lane; i < 256; i += 32) {
        long long v = p[i];
        if (v < 0 || v >= NODE_LEN) bad = 1;
    }
    unsigned m = __ballot_sync(0xffffffffu, bad);
    if (lane == 0) g_is64 = (m == 0) ? 1 : 0;
}
__device__ __forceinline__ long long load_idx(const void* p, long long i) {
    return g_is64 ? ((const long long*)p)[i] : (long long)((const int*)p)[i];
}

// ---------------- CSR build ----------------
__global__ void enc_hist_kernel(const void* __restrict__ rows, long long nnz) {
    long long e = (long long)blockIdx.x * blockDim.x + threadIdx.x;
    if (e >= nnz) return;
    atomicAdd(&g_cnt[load_idx(rows, e)], 1);
}
__global__ void enc_fill_kernel(const void* __restrict__ rows, const void* __restrict__ cols,
                                const float* __restrict__ vals, long long nnz) {
    long long e = (long long)blockIdx.x * blockDim.x + threadIdx.x;
    if (e >= nnz) return;
    int r = (int)load_idx(rows, e);
    int pos = atomicAdd(&g_fill[r], 1);
    g_ecol[pos] = (int)load_idx(cols, e);
    g_eval[pos] = vals[e];
}
// single-block exclusive scan: cnt[0..n) -> off[0..n], fill[0..n)
__global__ void scan_kernel(const int* __restrict__ cnt, int* __restrict__ off,
                            int* __restrict__ fill, int n) {
    __shared__ int part[1024];
    int t = threadIdx.x;
    int chunk = (n + 1023) >> 10;
    int lo = t * chunk, hi = lo + chunk;
    if (hi > n) hi = n;
    int s = 0;
    for (int i = lo; i < hi; i++) s += cnt[i];
    part[t] = s;
    __syncthreads();
    for (int d = 1; d < 1024; d <<= 1) {
        int add = (t >= d) ? part[t - d] : 0;
        __syncthreads();
        part[t] += add;
        __syncthreads();
    }
    int run = part[t] - s;                 // exclusive prefix at chunk start
    for (int i = lo; i < hi; i++) {
        off[i] = run; fill[i] = run;
        run += cnt[i];
    }
    if (t == 1023) off[n] = part[1023];
}
__global__ void mend_hist_edges_kernel(const void* __restrict__ edges, int E) {
    int e = blockIdx.x * blockDim.x + threadIdx.x;
    if (e >= E) return;
    int lo = (int)load_idx(edges, 2LL * e);
    int hi = (int)load_idx(edges, 2LL * e + 1);
    atomicAdd(&g_cnt[lo], 1);
    atomicAdd(&g_cnt[hi], 1);
}
__global__ void mend_hist_new_kernel(const int* __restrict__ pdeg) {
    int t = blockIdx.x * blockDim.x + threadIdx.x;
    if (t >= NNODES * NPRED) return;
    int node = t / NPRED, j = t - node * NPRED;
    if (j < pdeg[node]) {
        atomicAdd(&g_cnt[node], 1);
        g_cnt[NNODES + t] = 1;             // unique writer (post-memset)
    }
}
__global__ void mend_fill_edges_kernel(const void* __restrict__ edges, int E) {
    int e = blockIdx.x * blockDim.x + threadIdx.x;
    if (e >= E) return;
    int lo = (int)load_idx(edges, 2LL * e);
    int hi = (int)load_idx(edges, 2LL * e + 1);
    int p0 = atomicAdd(&g_fill[lo], 1);
    g_mcol[p0] = hi;
    int p1 = atomicAdd(&g_fill[hi], 1);
    g_mcol[p1] = lo;
}
__global__ void mend_fill_new_kernel(const int* __restrict__ pdeg) {
    int t = blockIdx.x * blockDim.x + threadIdx.x;
    if (t >= NNODES * NPRED) return;
    int node = t / NPRED, j = t - node * NPRED;
    if (j < pdeg[node]) {
        int p0 = atomicAdd(&g_fill[node], 1);
        g_mcol[p0] = NNODES + t;
        g_mcol[g_off_mend[NNODES + t]] = node;   // gen row has exactly 1 entry
    }
}

// ---------------- gather SpMM (warp per row) ----------------
// ENC: y = relu(sum(v*x[c]) + bias)        (vals from adj, loops included in CSR)
// MEND: y = relu((sum(x[c]) + x[r]) / (1 + deg) + bias)
template <int D, bool MEND>
__global__ void spmm_gather_kernel(const int* __restrict__ off, const int* __restrict__ cols,
                                   const float* __restrict__ vals,
                                   const float* __restrict__ x, const float* __restrict__ bias,
                                   float* __restrict__ y, int nrows)
{
    int w = (int)(((long long)blockIdx.x * blockDim.x + threadIdx.x) >> 5);
    int lane = threadIdx.x & 31;
    if (w >= nrows) return;
    int e0 = off[w], e1 = off[w + 1];

    if (D == 256) {
        float a[8] = {0, 0, 0, 0, 0, 0, 0, 0};
        const int cb = lane * 4;
        for (int e = e0; e < e1; e++) {
            long long c = cols[e];
            float4 t0 = *(const float4*)(x + c * 256 + cb);
            float4 t1 = *(const float4*)(x + c * 256 + 128 + cb);
            if (MEND) {
                a[0] += t0.x; a[1] += t0.y; a[2] += t0.z; a[3] += t0.w;
                a[4] += t1.x; a[5] += t1.y; a[6] += t1.z; a[7] += t1.w;
            } else {
                float v = vals[e];
                a[0] += v * t0.x; a[1] += v * t0.y; a[2] += v * t0.z; a[3] += v * t0.w;
                a[4] += v * t1.x; a[5] += v * t1.y; a[6] += v * t1.z; a[7] += v * t1.w;
            }
        }
        float4 o0, o1;
        if (MEND) {
            float inv = 1.0f / (1.0f + (float)(e1 - e0));
            const float* xr = x + (long long)w * 256;
            o0.x = fmaxf((a[0] + xr[cb + 0]) * inv + bias[cb + 0], 0.f);
            o0.y = fmaxf((a[1] + xr[cb + 1]) * inv + bias[cb + 1], 0.f);
            o0.z = fmaxf((a[2] + xr[cb + 2]) * inv + bias[cb + 2], 0.f);
            o0.w = fmaxf((a[3] + xr[cb + 3]) * inv + bias[cb + 3], 0.f);
            o1.x = fmaxf((a[4] + xr[128 + cb + 0]) * inv + bias[128 + cb + 0], 0.f);
            o1.y = fmaxf((a[5] + xr[128 + cb + 1]) * inv + bias[128 + cb + 1], 0.f);
            o1.z = fmaxf((a[6] + xr[128 + cb + 2]) * inv + bias[128 + cb + 2], 0.f);
            o1.w = fmaxf((a[7] + xr[128 + cb + 3]) * inv + bias[128 + cb + 3], 0.f);
        } else {
            o0.x = fmaxf(a[0] + bias[cb + 0], 0.f);
            o0.y = fmaxf(a[1] + bias[cb + 1], 0.f);
            o0.z = fmaxf(a[2] + bias[cb + 2], 0.f);
            o0.w = fmaxf(a[3] + bias[cb + 3], 0.f);
            o1.x = fmaxf(a[4] + bias[128 + cb + 0], 0.f);
            o1.y = fmaxf(a[5] + bias[128 + cb + 1], 0.f);
            o1.z = fmaxf(a[6] + bias[128 + cb + 2], 0.f);
            o1.w = fmaxf(a[7] + bias[128 + cb + 3], 0.f);
        }
        *(float4*)(y + (long long)w * 256 + cb) = o0;
        *(float4*)(y + (long long)w * 256 + 128 + cb) = o1;
    } else if (D == 64) {
        float a0 = 0.f, a1 = 0.f;
        const int cb = lane * 2;
        for (int e = e0; e < e1; e++) {
            long long c = cols[e];
            float2 t = *(const float2*)(x + c * 64 + cb);
            if (MEND) { a0 += t.x; a1 += t.y; }
            else { float v = vals[e]; a0 += v * t.x; a1 += v * t.y; }
        }
        float2 o;
        if (MEND) {
            float inv = 1.0f / (1.0f + (float)(e1 - e0));
            const float* xr = x + (long long)w * 64;
            o.x = fmaxf((a0 + xr[cb + 0]) * inv + bias[cb + 0], 0.f);
            o.y = fmaxf((a1 + xr[cb + 1]) * inv + bias[cb + 1], 0.f);
        } else {
            o.x = fmaxf(a0 + bias[cb + 0], 0.f);
            o.y = fmaxf(a1 + bias[cb + 1], 0.f);
        }
        *(float2*)(y + (long long)w * 64 + cb) = o;
    } else {  // D == 16
        if (lane < 16) {
            float a = 0.f;
            for (int e = e0; e < e1; e++)
                a += x[(long long)cols[e] * 16 + lane];
            float inv = 1.0f / (1.0f + (float)(e1 - e0));
            float v = (a + x[(long long)w * 16 + lane]) * inv + bias[lane];
            y[(long long)w * 16 + lane] = fmaxf(v, 0.f);
        }
    }
}

// ---------------- weight transpose + tf32 round: W[K,N] -> WT[Npad,Kpad] ----
__global__ void transpose_tf32_kernel(const float* __restrict__ W, float* __restrict__ WT,
                                      int K, int N, int Kpad, int Npad) {
    __shared__ float tile[32][33];
    int kb = blockIdx.x * 32, nb = blockIdx.y * 32;
    int tx = threadIdx.x, ty = threadIdx.y;   // 32 x 8
#pragma unroll
    for (int i = 0; i < 4; i++) {
        int k = kb + ty + i * 8, n = nb + tx;
        tile[ty + i * 8][tx] = (k < K && n < N) ? W[(long long)k * N + n] : 0.0f;
    }
    __syncthreads();
#pragma unroll
    for (int i = 0; i < 4; i++) {
        int n = nb + ty + i * 8, k = kb + tx;
        if (n < Npad && k < Kpad)
            WT[(long long)n * Kpad + k] = to_tf32(tile[tx][ty + i * 8]);
    }
}

// ---------------- tf32 mma.sync GEMM: C[M,N] = A[M,K] @ W[K,N] --------------
#define GSTAGES 4
#define G_STRIDE_F 36
#define G_MAT_BYTES (128 * G_STRIDE_F * 4)          // 18432
#define G_STAGE_BYTES (2 * G_MAT_BYTES)             // 36864
#define G_SMEM_TOTAL (GSTAGES * G_STAGE_BYTES)      // 147456

template <int EPI, bool SPLIT>
__global__ void __launch_bounds__(256, 1) mma_gemm_kernel(
    const float* __restrict__ A, const float* __restrict__ Agen, int splitRows,
    const float* __restrict__ BT, const float* __restrict__ bias,
    float* __restrict__ C, int M, int N, int K, int Kpad)
{
    extern __shared__ char smem[];
    const uint32_t sbase = smem_u32(smem);
    const int tid = threadIdx.x;
    const int wid = tid >> 5, lane = tid & 31;
    const int gid = lane >> 2, tig = lane & 3;
    const int warp_m = wid & 3, warp_n = wid >> 2;
    const int m0 = blockIdx.y * 128, n0 = blockIdx.x * 128;

    const int crow = tid >> 1;
    const int cboff = (tid & 1) * 64;

    const float* aptr;
    {
        int r = m0 + crow;
        int rr = (r < M) ? r : (M - 1);
        if (!SPLIT || rr < splitRows) {
            aptr = A + (long long)rr * K;
        } else {
            int q = rr - splitRows;
            aptr = Agen + (long long)(q / NPRED) * GENF + (long long)(q % NPRED) * FEAT;
        }
    }
    const float* bptr = BT + (long long)(n0 + crow) * Kpad;

    const uint32_t sA_wr = sbase + (uint32_t)crow * 144u + (uint32_t)cboff;
    const uint32_t sB_wr = sA_wr + G_MAT_BYTES;

    const int nChunks = (K + 31) >> 5;

    auto issue = [&](int chunk) {
        int s = chunk & (GSTAGES - 1);
        int k0 = chunk << 5;
        uint32_t da = sA_wr + (uint32_t)s * G_STAGE_BYTES;
        uint32_t db = sB_wr + (uint32_t)s * G_STAGE_BYTES;
        const char* ga = (const char*)(aptr + k0) + cboff;
        const char* gb = (const char*)(bptr + k0) + cboff;
        int avail = K * 4 - (k0 * 4 + cboff);
        if (avail >= 64) {
#pragma unroll
            for (int i = 0; i < 4; i++) CP_ASYNC16(da + i * 16, ga + i * 16);
        } else {
#pragma unroll
            for (int i = 0; i < 4; i++) {
                int b = avail - i * 16;
                int bytes = b >= 16 ? 16 : (b > 0 ? b : 0);
                const char* src = (bytes > 0) ? (ga + i * 16) : (const char*)aptr;
                CP_ASYNC16Z(da + i * 16, src, bytes);
            }
        }
#pragma unroll
        for (int i = 0; i < 4; i++) CP_ASYNC16(db + i * 16, gb + i * 16);
        CP_COMMIT();
    };

    float acc[2][8][4];
#pragma unroll
    for (int f = 0; f < 2; f++)
#pragma unroll
        for (int j = 0; j < 8; j++)
#pragma unroll
            for (int q = 0; q < 4; q++) acc[f][j][q] = 0.0f;

    int pro = (GSTAGES - 1 < nChunks) ? GSTAGES - 1 : nChunks;
    for (int s = 0; s < pro; s++) issue(s);
    for (int s = pro; s < GSTAGES - 1; s++) CP_COMMIT();

    uint32_t a_off[2];
#pragma unroll
    for (int f = 0; f < 2; f++) {
        uint32_t row = (uint32_t)(warp_m * 32 + f * 16 + (lane & 15));
        uint32_t colb = (uint32_t)((lane >> 4) << 4);
        a_off[f] = row * 144u + colb;
    }
    uint32_t b_off[4];
#pragma unroll
    for (int jp = 0; jp < 4; jp++) {
        uint32_t row = (uint32_t)(warp_n * 64 + jp * 16 + ((lane >> 4) << 3) + (lane & 7));
        uint32_t colb = (uint32_t)(((lane >> 3) & 1) << 4);
        b_off[jp] = row * 144u + colb;
    }

    for (int i = 0; i < nChunks; i++) {
        if (i + GSTAGES - 1 < nChunks) issue(i + GSTAGES - 1);
        else CP_COMMIT();
        CP_WAIT(GSTAGES - 1);
        __syncthreads();

        uint32_t sA = sbase + (uint32_t)(i & (GSTAGES - 1)) * G_STAGE_BYTES;
        uint32_t sB = sA + G_MAT_BYTES;
#pragma unroll
        for (int kk = 0; kk < 32; kk += 8) {
            uint32_t afr[2][4];
            ldsm_x4(sA + a_off[0] + kk * 4, afr[0]);
            ldsm_x4(sA + a_off[1] + kk * 4, afr[1]);
#pragma unroll
            for (int jp = 0; jp < 4; jp++) {
                uint32_t br[4];
                ldsm_x4(sB + b_off[jp] + kk * 4, br);
                mma_tf32(acc[0][2 * jp + 0], afr[0], br[0], br[1]);
                mma_tf32(acc[1][2 * jp + 0], afr[1], br[0], br[1]);
                mma_tf32(acc[0][2 * jp + 1], afr[0], br[2], br[3]);
                mma_tf32(acc[1][2 * jp + 1], afr[1], br[2], br[3]);
            }
        }
        __syncthreads();
    }

#pragma unroll
    for (int f = 0; f < 2; f++) {
        int r0 = m0 + warp_m * 32 + f * 16 + gid;
#pragma unroll
        for (int j = 0; j < 8; j++) {
            int c = n0 + warp_n * 64 + j * 8 + tig * 2;
            if (c >= N) continue;
            float v0 = acc[f][j][0], v1 = acc[f][j][1];
            float v2 = acc[f][j][2], v3 = acc[f][j][3];
            if (EPI >= 1) {
                float bb0 = bias[c], bb1 = bias[c + 1];
                v0 += bb0; v1 += bb1; v2 += bb0; v3 += bb1;
            }
            if (EPI == 1) {
                v0 = fmaxf(v0, 0.f); v1 = fmaxf(v1, 0.f);
                v2 = fmaxf(v2, 0.f); v3 = fmaxf(v3, 0.f);
            }
            if (EPI == 2) {
                v0 = tanhf(v0); v1 = tanhf(v1);
                v2 = tanhf(v2); v3 = tanhf(v3);
            }
            if (r0 < M)     *(float2*)(C + (long long)r0 * N + c)       = make_float2(v0, v1);
            if (r0 + 8 < M) *(float2*)(C + (long long)(r0 + 8) * N + c) = make_float2(v2, v3);
        }
    }
}

// ---------------- SIMT SGEMM (precision-critical / small GEMMs) ----
#define BM 128
#define BN 128
#define BK 8
template <int EPI>
__global__ void __launch_bounds__(256, 2) sgemm_kernel(
    const float* __restrict__ A, const float* __restrict__ B,
    const float* __restrict__ bias, float* __restrict__ C, int M, int N, int K)
{
    __shared__ float As[BK][BM];
    __shared__ float Bs[BK][BN];
    const int tid = threadIdx.x;
    const int tx = tid & 15, ty = tid >> 4;
    const int rbase = blockIdx.y * BM, cbase = blockIdx.x * BN;
    float acc[8][8];
#pragma unroll
    for (int i = 0; i < 8; i++)
#pragma unroll
        for (int j = 0; j < 8; j++) acc[i][j] = 0.0f;
    const int arow = tid >> 1, acol = (tid & 1) * 4;
    const int brow = tid >> 5, bcol = (tid & 31) * 4;
    const float* arowptr = (rbase + arow < M) ? A + (long long)(rbase + arow) * K : nullptr;

    for (int kt = 0; kt < K; kt += BK) {
        float4 av = make_float4(0.f, 0.f, 0.f, 0.f);
        if (arowptr) {
            int kc = kt + acol;
            if (kc + 3 < K) av = *(const float4*)(arowptr + kc);
            else {
                if (kc + 0 < K) av.x = arowptr[kc + 0];
                if (kc + 1 < K) av.y = arowptr[kc + 1];
                if (kc + 2 < K) av.z = arowptr[kc + 2];
                if (kc + 3 < K) av.w = arowptr[kc + 3];
            }
        }
        As[acol + 0][arow] = av.x; As[acol + 1][arow] = av.y;
        As[acol + 2][arow] = av.z; As[acol + 3][arow] = av.w;
        float4 bv = make_float4(0.f, 0.f, 0.f, 0.f);
        {
            int kr = kt + brow, cc = cbase + bcol;
            if (kr < K) {
                const float* bp = B + (long long)kr * N + cc;
                if (cc + 3 < N) bv = *(const float4*)bp;
                else {
                    if (cc + 0 < N) bv.x = bp[0];
                    if (cc + 1 < N) bv.y = bp[1];
                    if (cc + 2 < N) bv.z = bp[2];
                    if (cc + 3 < N) bv.w = bp[3];
                }
            }
        }
        *(float4*)&Bs[brow][bcol] = bv;
        __syncthreads();
#pragma unroll
        for (int k = 0; k < BK; k++) {
            float ra[8], rb[8];
            *(float4*)&ra[0] = *(const float4*)&As[k][ty * 4];
            *(float4*)&ra[4] = *(const float4*)&As[k][64 + ty * 4];
            *(float4*)&rb[0] = *(const float4*)&Bs[k][tx * 4];
            *(float4*)&rb[4] = *(const float4*)&Bs[k][64 + tx * 4];
#pragma unroll
            for (int i = 0; i < 8; i++)
#pragma unroll
                for (int j = 0; j < 8; j++) acc[i][j] += ra[i] * rb[j];
        }
        __syncthreads();
    }
#pragma unroll
    for (int i = 0; i < 8; i++) {
        int r = rbase + ((i < 4) ? (ty * 4 + i) : (64 + ty * 4 + i - 4));
        if (r >= M) continue;
#pragma unroll
        for (int j = 0; j < 8; j++) {
            int c = cbase + ((j < 4) ? (tx * 4 + j) : (64 + tx * 4 + j - 4));
            if (c >= N) continue;
            float v = acc[i][j];
            if (EPI >= 1) v += bias[c];
            if (EPI == 1) v = fmaxf(v, 0.0f);
            C[(long long)r * N + c] = v;
        }
    }
}

// ---------------- skinny GEMM for gc4 ----------------
__global__ void skinny16_kernel(const float* __restrict__ X, const float* __restrict__ W,
                                float* __restrict__ C, int M)
{
    __shared__ float Ws[256 * 16];
    int tid = threadIdx.x;   // 128
    for (int i = tid; i < 256 * 16; i += 128) Ws[i] = W[i];
    __syncthreads();
    int r = blockIdx.x * 128 + tid;
    if (r >= M) return;
    const float* x = X + (long long)r * 256;
    float acc[16];
#pragma unroll
    for (int q = 0; q < 16; q++) acc[q] = 0.0f;
    for (int k = 0; k < 256; k += 4) {
        float4 a = *(const float4*)(x + k);
#pragma unroll
        for (int q = 0; q < 16; q++)
            acc[q] += a.x * Ws[(k + 0) * 16 + q] + a.y * Ws[(k + 1) * 16 + q]
                    + a.z * Ws[(k + 2) * 16 + q] + a.w * Ws[(k + 3) * 16 + q];
    }
    float* co = C + (long long)r * 16;
#pragma unroll
    for (int q = 0; q < 16; q += 4)
        *(float4*)(co + q) = make_float4(acc[q], acc[q + 1], acc[q + 2], acc[q + 3]);
}

// ---------------- misc ----------------
__global__ void degree_kernel(const float* __restrict__ z, const float* __restrict__ Wr,
                              const float* __restrict__ br, float* __restrict__ deg_out,
                              int* __restrict__ pdeg, int n)
{
    int r = blockIdx.x * (blockDim.x >> 5) + (threadIdx.x >> 5);
    int lane = threadIdx.x & 31;
    if (r >= n) return;
    float s = z[(long long)r * LAT + lane] * Wr[lane]
            + z[(long long)r * LAT + 32 + lane] * Wr[32 + lane];
#pragma unroll
    for (int o = 16; o; o >>= 1) s += __shfl_xor_sync(0xffffffffu, s, o);
    if (lane == 0) {
        float d = fmaxf(s + br[0], 0.0f);
        deg_out[r] = d;
        int pi = (int)d;
        if (pi > NPRED) pi = NPRED;
        pdeg[r] = pi;
    }
}

__global__ void add_kernel(float* __restrict__ o, const float* __restrict__ a,
                           const float* __restrict__ b, long long n)
{
    long long i = (long long)blockIdx.x * blockDim.x + threadIdx.x;
    if (i < n) o[i] = a[i] + b[i];
}

// ---------------- host ----------------
static inline int cdiv(long long a, long long b) { return (int)((a + b - 1) / b); }

extern "C" void kernel_launch(void* const* d_in, const int* in_sizes, int n_in,
                              void* d_out, int out_size)
{
    const float* feat     = (const float*)d_in[0];
    const void*  edges    = d_in[1];
    const void*  adj_rows = d_in[2];
    const void*  adj_cols = d_in[3];
    const float* adj_vals = (const float*)d_in[4];
    const float* noise    = (const float*)d_in[5];
    const float* W_gc1 = (const float*)d_in[6];   const float* b_gc1 = (const float*)d_in[7];
    const float* W_gc2 = (const float*)d_in[8];   const float* b_gc2 = (const float*)d_in[9];
    const float* W_reg = (const float*)d_in[10];  const float* b_reg = (const float*)d_in[11];
    const float* W_fc1 = (const float*)d_in[12];  const float* b_fc1 = (const float*)d_in[13];
    const float* W_fc2 = (const float*)d_in[14];  const float* b_fc2 = (const float*)d_in[15];
    const float* W_flat = (const float*)d_in[16]; const float* b_flat = (const float*)d_in[17];
    const float* W_gc3 = (const float*)d_in[18];  const float* b_gc3 = (const float*)d_in[19];
    const float* W_gc4 = (const float*)d_in[20];  const float* b_gc4 = (const float*)d_in[21];

    float* out = (float*)d_out;
    float* out_deg = out;
    float* out_gen = out + OUT_GEN_OFF;
    float* out_nc  = out + OUT_NC_OFF;

    const long long nnz_adj = in_sizes[2];
    const int E = in_sizes[1] / 2;

    void* p;
    float *bufA, *bufB, *z, *zn, *g1, *g2, *c7;
    float *wt_fc2, *wt_flat, *wt_gc3;
    int *pdeg, *cnt, *fill, *off_enc, *off_mend, *ecol, *mcol;
    float *eval;
    cudaGetSymbolAddress(&p, g_bufA);  bufA  = (float*)p;
    cudaGetSymbolAddress(&p, g_bufB);  bufB  = (float*)p;
    cudaGetSymbolAddress(&p, g_z);     z     = (float*)p;
    cudaGetSymbolAddress(&p, g_zn);    zn    = (float*)p;
    cudaGetSymbolAddress(&p, g_g1);    g1    = (float*)p;
    cudaGetSymbolAddress(&p, g_g2);    g2    = (float*)p;
    cudaGetSymbolAddress(&p, g_c7);    c7    = (float*)p;
    cudaGetSymbolAddress(&p, g_pdeg);  pdeg  = (int*)p;
    cudaGetSymbolAddress(&p, g_cnt);   cnt   = (int*)p;
    cudaGetSymbolAddress(&p, g_fill);  fill  = (int*)p;
    cudaGetSymbolAddress(&p, g_off_enc);  off_enc  = (int*)p;
    cudaGetSymbolAddress(&p, g_off_mend); off_mend = (int*)p;
    cudaGetSymbolAddress(&p, g_ecol);  ecol  = (int*)p;
    cudaGetSymbolAddress(&p, g_eval);  eval  = (float*)p;
    cudaGetSymbolAddress(&p, g_mcol);  mcol  = (int*)p;
    cudaGetSymbolAddress(&p, g_wt_fc2);  wt_fc2  = (float*)p;
    cudaGetSymbolAddress(&p, g_wt_flat); wt_flat = (float*)p;
    cudaGetSymbolAddress(&p, g_wt_gc3);  wt_gc3  = (float*)p;

    cudaFuncSetAttribute((const void*)mma_gemm_kernel<1, false>,
                         cudaFuncAttributeMaxDynamicSharedMemorySize, G_SMEM_TOTAL);
    cudaFuncSetAttribute((const void*)mma_gemm_kernel<2, false>,
                         cudaFuncAttributeMaxDynamicSharedMemorySize, G_SMEM_TOTAL);
    cudaFuncSetAttribute((const void*)mma_gemm_kernel<0, true>,
                         cudaFuncAttributeMaxDynamicSharedMemorySize, G_SMEM_TOTAL);

    const int TB = 256;
    dim3 tblk(32, 8);

    // 0) index-width detection + weight transposes
    detect_idx_kernel<<<1, 32>>>(adj_rows);
    transpose_tf32_kernel<<<dim3(cdiv(256, 32), cdiv(2048, 32)), tblk>>>(W_fc2, wt_fc2, 256, 2048, 256, 2048);
    transpose_tf32_kernel<<<dim3(cdiv(2048, 32), cdiv(2560, 32)), tblk>>>(W_flat, wt_flat, 2048, 2500, 2048, 2560);
    transpose_tf32_kernel<<<dim3(cdiv(512, 32), cdiv(256, 32)), tblk>>>(W_gc3, wt_gc3, 500, 256, 512, 256);

    // 0b) encoder CSR build
    cudaMemsetAsync(cnt, 0, NNODES * sizeof(int));
    enc_hist_kernel<<<cdiv(nnz_adj, TB), TB>>>(adj_rows, nnz_adj);
    scan_kernel<<<1, 1024>>>(cnt, off_enc, fill, NNODES);
    enc_fill_kernel<<<cdiv(nnz_adj, TB), TB>>>(adj_rows, adj_cols, adj_vals, nnz_adj);

    // 1) XW1 = feat @ W_gc1 (fp32 exact — feeds the int(degree) cliff)
    {
        dim3 grid(cdiv(HID, BN), cdiv(NNODES, BM));
        sgemm_kernel<0><<<grid, TB>>>(feat, W_gc1, nullptr, bufA, NNODES, HID, FEAT);
    }
    // 2) h = relu(spmm + b1) — CSR gather, fused bias+relu
    spmm_gather_kernel<256, false><<<cdiv(NNODES, 8), TB>>>(off_enc, ecol, eval, bufA, b_gc1, bufB, NNODES);
    // 3) hW2 = h @ W_gc2
    {
        dim3 grid(cdiv(LAT, BN), cdiv(NNODES, BM));
        sgemm_kernel<0><<<grid, TB>>>(bufB, W_gc2, nullptr, bufA, NNODES, LAT, HID);
    }
    // 4) z = relu(spmm + b2) — CSR gather
    spmm_gather_kernel<64, false><<<cdiv(NNODES, 8), TB>>>(off_enc, ecol, eval, bufA, b_gc2, z, NNODES);
    // 5) degree + pred_deg
    degree_kernel<<<cdiv(NNODES, TB / 32), TB>>>(z, W_reg, b_reg, out_deg, pdeg, NNODES);
    // 5b) mend CSR build (needs pdeg)
    cudaMemsetAsync(cnt, 0, NODE_LEN * sizeof(int));
    mend_hist_edges_kernel<<<cdiv(E, TB), TB>>>(edges, E);
    mend_hist_new_kernel<<<cdiv(NNODES * NPRED, TB), TB>>>(pdeg);
    scan_kernel<<<1, 1024>>>(cnt, off_mend, fill, NODE_LEN);
    mend_fill_edges_kernel<<<cdiv(E, TB), TB>>>(edges, E);
    mend_fill_new_kernel<<<cdiv(NNODES * NPRED, TB), TB>>>(pdeg);
    // 6) zn = z + noise
    add_kernel<<<cdiv((long long)NNODES * LAT, TB), TB>>>(zn, z, noise, (long long)NNODES * LAT);
    // 7) g1 = relu(zn @ W_fc1 + b) — small K, SIMT
    {
        dim3 grid(cdiv(FC1N, BN), cdiv(NNODES, BM));
        sgemm_kernel<1><<<grid, TB>>>(zn, W_fc1, b_fc1, g1, NNODES, FC1N, LAT);
    }
    // 8) g2 = relu(g1 @ W_fc2 + b) — tf32 mma
    {
        dim3 grid(FC2N / 128, cdiv(NNODES, 128));
        mma_gemm_kernel<1, false><<<grid, 256, G_SMEM_TOTAL>>>(
            g1, nullptr, 0, wt_fc2, b_fc2, g2, NNODES, FC2N, FC1N, 256);
    }
    // 9) gen_feat = tanh(g2 @ W_flat + b) — tf32 mma
    {
        dim3 grid(2560 / 128, cdiv(NNODES, 128));
        mma_gemm_kernel<2, false><<<grid, 256, G_SMEM_TOTAL>>>(
            g2, nullptr, 0, wt_flat, b_flat, out_gen, NNODES, GENF, FC2N, 2048);
    }
    // 10) fillW3 = fill_feats @ W_gc3 — tf32 mma with row indirection
    {
        dim3 grid(HID / 128, cdiv(NODE_LEN, 128));
        mma_gemm_kernel<0, true><<<grid, 256, G_SMEM_TOTAL>>>(
            feat, out_gen, NNODES, wt_gc3, nullptr, bufA, NODE_LEN, HID, FEAT, 512);
    }
    // 12) mend layer 1 — CSR gather, fused normalize+bias+relu
    spmm_gather_kernel<256, true><<<cdiv(NODE_LEN, 8), TB>>>(off_mend, mcol, nullptr, bufA, b_gc3, bufB, NODE_LEN);
    // 13) c7 = h2 @ W_gc4 — skinny N=16
    skinny16_kernel<<<cdiv(NODE_LEN, 128), 128>>>(bufB, W_gc4, c7, NODE_LEN);
    // 14) mend layer 2 — CSR gather
    spmm_gather_kernel<16, true><<<cdiv(NODE_LEN, 8), TB>>>(off_mend, mcol, nullptr, c7, b_gc4, out_nc, NODE_LEN);

    (void)n_in; (void)out_size;
}

// round 9
// speedup vs baseline: 1.9131x; 1.8651x over previous
#include <cuda_runtime.h>
#include <cuda_fp16.h>
#include <cstdint>

// ---------------- problem constants ----------------
#define NNODES   20000
#define FEAT     500
#define HID      256
#define LAT      64
#define NPRED    5
#define NCLS     16
#define NODE_LEN (NNODES + NNODES * NPRED)      // 120000
#define GENF     (NPRED * FEAT)                 // 2500
#define FC1N     256
#define FC2N     2048

#define OUT_GEN_OFF ((long long)NNODES)
#define OUT_NC_OFF  ((long long)NNODES + (long long)NNODES * GENF)

// ---------------- scratch (static device globals; no allocation) ------------
__device__ float g_bufA[(size_t)NODE_LEN * HID];
__device__ float g_bufB[(size_t)NODE_LEN * HID];
__device__ float g_z[(size_t)NNODES * LAT];
__device__ float g_zn[(size_t)NNODES * LAT];
__device__ float g_c7[(size_t)NODE_LEN * NCLS];
__device__ int   g_pdeg[NNODES];
__device__ int   g_is64;
// fp16 operands
__device__ __half g_g1h[(size_t)NNODES * FC1N];
__device__ __half g_g2h[(size_t)NNODES * FC2N];
__device__ __half g_fillh[(size_t)NODE_LEN * 512];
__device__ __half g_wh_fc2[(size_t)2048 * 256];
__device__ __half g_wh_flat[(size_t)2560 * 2048];
__device__ __half g_wh_gc3[(size_t)256 * 512];
// CSR scratch
__device__ int   g_cnt[NODE_LEN];
__device__ int   g_fill[NODE_LEN];
__device__ int   g_off_enc[NNODES + 1];
__device__ int   g_off_mend[NODE_LEN + 1];
__device__ int   g_ecol[700000];
__device__ float g_eval[700000];
__device__ int   g_mcol[900000];

// ---------------- helpers ----------------
__device__ __forceinline__ uint32_t smem_u32(const void* p) {
    uint32_t a;
    asm("{ .reg .u64 t; cvta.to.shared.u64 t, %1; cvt.u32.u64 %0, t; }" : "=r"(a) : "l"(p));
    return a;
}
__device__ __forceinline__ void ldsm_x4(uint32_t addr, uint32_t* r) {
    asm volatile("ldmatrix.sync.aligned.m8n8.x4.shared.b16 {%0,%1,%2,%3}, [%4];"
                 : "=r"(r[0]), "=r"(r[1]), "=r"(r[2]), "=r"(r[3]) : "r"(addr));
}
__device__ __forceinline__ void mma_f16(float* c, const uint32_t* a, uint32_t b0, uint32_t b1) {
    asm volatile(
        "mma.sync.aligned.m16n8k16.row.col.f32.f16.f16.f32 "
        "{%0,%1,%2,%3}, {%4,%5,%6,%7}, {%8,%9}, {%0,%1,%2,%3};"
        : "+f"(c[0]), "+f"(c[1]), "+f"(c[2]), "+f"(c[3])
        : "r"(a[0]), "r"(a[1]), "r"(a[2]), "r"(a[3]), "r"(b0), "r"(b1));
}
#define CP_ASYNC16(dst, src) \
    asm volatile("cp.async.cg.shared.global [%0], [%1], 16;" :: "r"(dst), "l"(src))
#define CP_COMMIT() asm volatile("cp.async.commit_group;" ::: "memory")
#define CP_WAIT(n)  asm volatile("cp.async.wait_group %0;" :: "n"(n) : "memory")

// ---------------- index dtype detection ----------------
__global__ void detect_idx_kernel(const void* adj_rows) {
    int lane = threadIdx.x;
    const long long* p = (const long long*)adj_rows;
    int bad = 0;
    for (int i = lane; i < 256; i += 32) {
        long long v = p[i];
        if (v < 0 || v >= NODE_LEN) bad = 1;
    }
    unsigned m = __ballot_sync(0xffffffffu, bad);
    if (lane == 0) g_is64 = (m == 0) ? 1 : 0;
}
__device__ __forceinline__ long long load_idx(const void* p, long long i) {
    return g_is64 ? ((const long long*)p)[i] : (long long)((const int*)p)[i];
}

// ---------------- CSR build ----------------
__global__ void enc_hist_kernel(const void* __restrict__ rows, long long nnz) {
    long long e = (long long)blockIdx.x * blockDim.x + threadIdx.x;
    if (e >= nnz) return;
    atomicAdd(&g_cnt[load_idx(rows, e)], 1);
}
__global__ void enc_fill_kernel(const void* __restrict__ rows, const void* __restrict__ cols,
                                const float* __restrict__ vals, long long nnz) {
    long long e = (long long)blockIdx.x * blockDim.x + threadIdx.x;
    if (e >= nnz) return;
    int r = (int)load_idx(rows, e);
    int pos = atomicAdd(&g_fill[r], 1);
    g_ecol[pos] = (int)load_idx(cols, e);
    g_eval[pos] = vals[e];
}
__global__ void scan_kernel(const int* __restrict__ cnt, int* __restrict__ off,
                            int* __restrict__ fill, int n) {
    __shared__ int part[1024];
    int t = threadIdx.x;
    int chunk = (n + 1023) >> 10;
    int lo = t * chunk, hi = lo + chunk;
    if (hi > n) hi = n;
    int s = 0;
    for (int i = lo; i < hi; i++) s += cnt[i];
    part[t] = s;
    __syncthreads();
    for (int d = 1; d < 1024; d <<= 1) {
        int add = (t >= d) ? part[t - d] : 0;
        __syncthreads();
        part[t] += add;
        __syncthreads();
    }
    int run = part[t] - s;
    for (int i = lo; i < hi; i++) {
        off[i] = run; fill[i] = run;
        run += cnt[i];
    }
    if (t == 1023) off[n] = part[1023];
}
__global__ void mend_hist_edges_kernel(const void* __restrict__ edges, int E) {
    int e = blockIdx.x * blockDim.x + threadIdx.x;
    if (e >= E) return;
    int lo = (int)load_idx(edges, 2LL * e);
    int hi = (int)load_idx(edges, 2LL * e + 1);
    atomicAdd(&g_cnt[lo], 1);
    atomicAdd(&g_cnt[hi], 1);
}
__global__ void mend_hist_new_kernel(const int* __restrict__ pdeg) {
    int t = blockIdx.x * blockDim.x + threadIdx.x;
    if (t >= NNODES * NPRED) return;
    int node = t / NPRED, j = t - node * NPRED;
    if (j < pdeg[node]) {
        atomicAdd(&g_cnt[node], 1);
        g_cnt[NNODES + t] = 1;
    }
}
__global__ void mend_fill_edges_kernel(const void* __restrict__ edges, int E) {
    int e = blockIdx.x * blockDim.x + threadIdx.x;
    if (e >= E) return;
    int lo = (int)load_idx(edges, 2LL * e);
    int hi = (int)load_idx(edges, 2LL * e + 1);
    int p0 = atomicAdd(&g_fill[lo], 1);
    g_mcol[p0] = hi;
    int p1 = atomicAdd(&g_fill[hi], 1);
    g_mcol[p1] = lo;
}
__global__ void mend_fill_new_kernel(const int* __restrict__ pdeg) {
    int t = blockIdx.x * blockDim.x + threadIdx.x;
    if (t >= NNODES * NPRED) return;
    int node = t / NPRED, j = t - node * NPRED;
    if (j < pdeg[node]) {
        int p0 = atomicAdd(&g_fill[node], 1);
        g_mcol[p0] = NNODES + t;
        g_mcol[g_off_mend[NNODES + t]] = node;
    }
}

// ---------------- gather SpMM (warp per row) ----------------
template <int D, bool MEND>
__global__ void spmm_gather_kernel(const int* __restrict__ off, const int* __restrict__ cols,
                                   const float* __restrict__ vals,
                                   const float* __restrict__ x, const float* __restrict__ bias,
                                   float* __restrict__ y, int nrows)
{
    int w = (int)(((long long)blockIdx.x * blockDim.x + threadIdx.x) >> 5);
    int lane = threadIdx.x & 31;
    if (w >= nrows) return;
    int e0 = off[w], e1 = off[w + 1];

    if (D == 256) {
        float a[8] = {0, 0, 0, 0, 0, 0, 0, 0};
        const int cb = lane * 4;
        for (int e = e0; e < e1; e++) {
            long long c = cols[e];
            float4 t0 = *(const float4*)(x + c * 256 + cb);
            float4 t1 = *(const float4*)(x + c * 256 + 128 + cb);
            if (MEND) {
                a[0] += t0.x; a[1] += t0.y; a[2] += t0.z; a[3] += t0.w;
                a[4] += t1.x; a[5] += t1.y; a[6] += t1.z; a[7] += t1.w;
            } else {
                float v = vals[e];
                a[0] += v * t0.x; a[1] += v * t0.y; a[2] += v * t0.z; a[3] += v * t0.w;
                a[4] += v * t1.x; a[5] += v * t1.y; a[6] += v * t1.z; a[7] += v * t1.w;
            }
        }
        float4 o0, o1;
        if (MEND) {
            float inv = 1.0f / (1.0f + (float)(e1 - e0));
            const float* xr = x + (long long)w * 256;
            o0.x = fmaxf((a[0] + xr[cb + 0]) * inv + bias[cb + 0], 0.f);
            o0.y = fmaxf((a[1] + xr[cb + 1]) * inv + bias[cb + 1], 0.f);
            o0.z = fmaxf((a[2] + xr[cb + 2]) * inv + bias[cb + 2], 0.f);
            o0.w = fmaxf((a[3] + xr[cb + 3]) * inv + bias[cb + 3], 0.f);
            o1.x = fmaxf((a[4] + xr[128 + cb + 0]) * inv + bias[128 + cb + 0], 0.f);
            o1.y = fmaxf((a[5] + xr[128 + cb + 1]) * inv + bias[128 + cb + 1], 0.f);
            o1.z = fmaxf((a[6] + xr[128 + cb + 2]) * inv + bias[128 + cb + 2], 0.f);
            o1.w = fmaxf((a[7] + xr[128 + cb + 3]) * inv + bias[128 + cb + 3], 0.f);
        } else {
            o0.x = fmaxf(a[0] + bias[cb + 0], 0.f);
            o0.y = fmaxf(a[1] + bias[cb + 1], 0.f);
            o0.z = fmaxf(a[2] + bias[cb + 2], 0.f);
            o0.w = fmaxf(a[3] + bias[cb + 3], 0.f);
            o1.x = fmaxf(a[4] + bias[128 + cb + 0], 0.f);
            o1.y = fmaxf(a[5] + bias[128 + cb + 1], 0.f);
            o1.z = fmaxf(a[6] + bias[128 + cb + 2], 0.f);
            o1.w = fmaxf(a[7] + bias[128 + cb + 3], 0.f);
        }
        *(float4*)(y + (long long)w * 256 + cb) = o0;
        *(float4*)(y + (long long)w * 256 + 128 + cb) = o1;
    } else if (D == 64) {
        float a0 = 0.f, a1 = 0.f;
        const int cb = lane * 2;
        for (int e = e0; e < e1; e++) {
            long long c = cols[e];
            float2 t = *(const float2*)(x + c * 64 + cb);
            if (MEND) { a0 += t.x; a1 += t.y; }
            else { float v = vals[e]; a0 += v * t.x; a1 += v * t.y; }
        }
        float2 o;
        if (MEND) {
            float inv = 1.0f / (1.0f + (float)(e1 - e0));
            const float* xr = x + (long long)w * 64;
            o.x = fmaxf((a0 + xr[cb + 0]) * inv + bias[cb + 0], 0.f);
            o.y = fmaxf((a1 + xr[cb + 1]) * inv + bias[cb + 1], 0.f);
        } else {
            o.x = fmaxf(a0 + bias[cb + 0], 0.f);
            o.y = fmaxf(a1 + bias[cb + 1], 0.f);
        }
        *(float2*)(y + (long long)w * 64 + cb) = o;
    } else {
        if (lane < 16) {
            float a = 0.f;
            for (int e = e0; e < e1; e++)
                a += x[(long long)cols[e] * 16 + lane];
            float inv = 1.0f / (1.0f + (float)(e1 - e0));
            float v = (a + x[(long long)w * 16 + lane]) * inv + bias[lane];
            y[(long long)w * 16 + lane] = fmaxf(v, 0.f);
        }
    }
}

// ---------------- weight transpose -> half: W[K,N] -> WT[Npad,Kpad] --------
__global__ void transpose_half_kernel(const float* __restrict__ W, __half* __restrict__ WT,
                                      int K, int N, int Kpad, int Npad) {
    __shared__ float tile[32][33];
    int kb = blockIdx.x * 32, nb = blockIdx.y * 32;
    int tx = threadIdx.x, ty = threadIdx.y;   // 32 x 8
#pragma unroll
    for (int i = 0; i < 4; i++) {
        int k = kb + ty + i * 8, n = nb + tx;
        tile[ty + i * 8][tx] = (k < K && n < N) ? W[(long long)k * N + n] : 0.0f;
    }
    __syncthreads();
#pragma unroll
    for (int i = 0; i < 4; i++) {
        int n = nb + ty + i * 8, k = kb + tx;
        if (n < Npad && k < Kpad)
            WT[(long long)n * Kpad + k] = __float2half_rn(tile[tx][ty + i * 8]);
    }
}

// feat -> fillh rows [0, NNODES), padded K=512
__global__ void feat_to_fillh_kernel(const float* __restrict__ feat, __half* __restrict__ fillh) {
    long long i = (long long)blockIdx.x * blockDim.x + threadIdx.x;
    if (i >= (long long)NNODES * 512) return;
    int r = (int)(i >> 9), c = (int)(i & 511);
    fillh[i] = (c < FEAT) ? __float2half_rn(feat[(long long)r * FEAT + c]) : __half(0.0f);
}

// ---------------- fp16 mma GEMM: C[M,N] = A[M,K] @ W[K,N] ------------------
// A: half [M,K] row-major; BT: half [Npad,Kpad] n-major.
// CTA tile 128x128, 8 warps (4m x 2n), warp tile 32x64, m16n8k16.
// Smem rows: 64B data + 16B pad (stride 80B) -> conflict-free ldmatrix.
#define HSTAGES 4
#define H_STRIDE_B 80
#define H_MAT_BYTES (128 * H_STRIDE_B)          // 10240
#define H_STAGE_BYTES (2 * H_MAT_BYTES)         // 20480
#define H_SMEM_TOTAL (HSTAGES * H_STAGE_BYTES)  // 81920

// EPI: 0 none, 1 bias+relu, 2 bias+tanh.  OUT: 0 f32 C, 1 half Ch, 2 f32 C + genh->fillh
template <int EPI, int OUT>
__global__ void __launch_bounds__(256, 2) hmma_gemm_kernel(
    const __half* __restrict__ A, const __half* __restrict__ BT,
    const float* __restrict__ bias,
    float* __restrict__ C, __half* __restrict__ Ch,
    int M, int N, int K, int Kpad)
{
    extern __shared__ char smem[];
    const uint32_t sbase = smem_u32(smem);
    const int tid = threadIdx.x;
    const int wid = tid >> 5, lane = tid & 31;
    const int gid = lane >> 2, tig = lane & 3;
    const int warp_m = wid & 3, warp_n = wid >> 2;
    const int m0 = blockIdx.y * 128, n0 = blockIdx.x * 128;

    const int crow = tid >> 1;
    const int cboff = (tid & 1) * 32;

    const __half* aptr;
    {
        int r = m0 + crow;
        int rr = (r < M) ? r : (M - 1);
        aptr = A + (long long)rr * K;
    }
    const __half* bptr = BT + (long long)(n0 + crow) * Kpad;

    const uint32_t sA_wr = sbase + (uint32_t)crow * H_STRIDE_B + (uint32_t)cboff;
    const uint32_t sB_wr = sA_wr + H_MAT_BYTES;

    const int nChunks = K >> 5;     // K always multiple of 32

    auto issue = [&](int chunk) {
        int s = chunk & (HSTAGES - 1);
        uint32_t da = sA_wr + (uint32_t)s * H_STAGE_BYTES;
        uint32_t db = sB_wr + (uint32_t)s * H_STAGE_BYTES;
        const char* ga = (const char*)aptr + chunk * 64 + cboff;
        const char* gb = (const char*)bptr + chunk * 64 + cboff;
        CP_ASYNC16(da, ga); CP_ASYNC16(da + 16, ga + 16);
        CP_ASYNC16(db, gb); CP_ASYNC16(db + 16, gb + 16);
        CP_COMMIT();
    };

    float acc[2][8][4];
#pragma unroll
    for (int f = 0; f < 2; f++)
#pragma unroll
        for (int j = 0; j < 8; j++)
#pragma unroll
            for (int q = 0; q < 4; q++) acc[f][j][q] = 0.0f;

    int pro = (HSTAGES - 1 < nChunks) ? HSTAGES - 1 : nChunks;
    for (int s = 0; s < pro; s++) issue(s);
    for (int s = pro; s < HSTAGES - 1; s++) CP_COMMIT();

    // A frag (16x16): mat0 rows m..m+7 k0-7, mat1 m+8..15 k0-7, mat2 m..m+7 k8-15, mat3 m+8..15 k8-15
    uint32_t a_off[2];
#pragma unroll
    for (int f = 0; f < 2; f++) {
        uint32_t row = (uint32_t)(warp_m * 32 + f * 16 + (lane & 15));
        uint32_t colb = (uint32_t)((lane >> 4) << 4);
        a_off[f] = row * H_STRIDE_B + colb;
    }
    // B frag pair (n-rows jp*16..+15): mat0 n0-7 k0-7, mat1 n0-7 k8-15, mat2 n8-15 k0-7, mat3 n8-15 k8-15
    uint32_t b_off[4];
#pragma unroll
    for (int jp = 0; jp < 4; jp++) {
        uint32_t row = (uint32_t)(warp_n * 64 + jp * 16 + ((lane >> 4) << 3) + (lane & 7));
        uint32_t colb = (uint32_t)(((lane >> 3) & 1) << 4);
        b_off[jp] = row * H_STRIDE_B + colb;
    }

    for (int i = 0; i < nChunks; i++) {
        if (i + HSTAGES - 1 < nChunks) issue(i + HSTAGES - 1);
        else CP_COMMIT();
        CP_WAIT(HSTAGES - 1);
        __syncthreads();

        uint32_t sA = sbase + (uint32_t)(i & (HSTAGES - 1)) * H_STAGE_BYTES;
        uint32_t sB = sA + H_MAT_BYTES;
#pragma unroll
        for (int kk = 0; kk < 2; kk++) {          // two k16 steps per 32-chunk
            uint32_t afr[2][4];
            ldsm_x4(sA + a_off[0] + kk * 32, afr[0]);
            ldsm_x4(sA + a_off[1] + kk * 32, afr[1]);
#pragma unroll
            for (int jp = 0; jp < 4; jp++) {
                uint32_t br[4];
                ldsm_x4(sB + b_off[jp] + kk * 32, br);
                mma_f16(acc[0][2 * jp + 0], afr[0], br[0], br[1]);
                mma_f16(acc[1][2 * jp + 0], afr[1], br[0], br[1]);
                mma_f16(acc[0][2 * jp + 1], afr[0], br[2], br[3]);
                mma_f16(acc[1][2 * jp + 1], afr[1], br[2], br[3]);
            }
        }
        __syncthreads();
    }

#pragma unroll
    for (int f = 0; f < 2; f++) {
#pragma unroll
        for (int rr = 0; rr < 2; rr++) {
            int r = m0 + warp_m * 32 + f * 16 + rr * 8 + gid;
            if (r >= M) continue;
#pragma unroll
            for (int j = 0; j < 8; j++) {
                int c = n0 + warp_n * 64 + j * 8 + tig * 2;
                if (c >= N) continue;
                float v0 = acc[f][j][rr * 2 + 0], v1 = acc[f][j][rr * 2 + 1];
                if (EPI >= 1) { v0 += bias[c]; v1 += bias[c + 1]; }
                if (EPI == 1) { v0 = fmaxf(v0, 0.f); v1 = fmaxf(v1, 0.f); }
                if (EPI == 2) { v0 = tanhf(v0); v1 = tanhf(v1); }
                if (OUT == 0) {
                    *(float2*)(C + (long long)r * N + c) = make_float2(v0, v1);
                } else if (OUT == 1) {
                    *(__half2*)(Ch + (long long)r * N + c) = __floats2half2_rn(v0, v1);
                } else {
                    *(float2*)(C + (long long)r * N + c) = make_float2(v0, v1);
                    int j5 = c / FEAT, cc = c - j5 * FEAT;   // c even, FEAT even -> pair same block
                    *(__half2*)(Ch + ((size_t)(NNODES + r * NPRED + j5) * 512 + cc)) =
                        __floats2half2_rn(v0, v1);
                }
            }
        }
    }
}

// ---------------- SIMT SGEMM (precision-critical / small GEMMs) ----
#define BM 128
#define BN 128
#define BK 8
template <int EPI, bool OUTH>
__global__ void __launch_bounds__(256, 2) sgemm_kernel(
    const float* __restrict__ A, const float* __restrict__ B,
    const float* __restrict__ bias, float* __restrict__ C, __half* __restrict__ Ch,
    int M, int N, int K)
{
    __shared__ float As[BK][BM];
    __shared__ float Bs[BK][BN];
    const int tid = threadIdx.x;
    const int tx = tid & 15, ty = tid >> 4;
    const int rbase = blockIdx.y * BM, cbase = blockIdx.x * BN;
    float acc[8][8];
#pragma unroll
    for (int i = 0; i < 8; i++)
#pragma unroll
        for (int j = 0; j < 8; j++) acc[i][j] = 0.0f;
    const int arow = tid >> 1, acol = (tid & 1) * 4;
    const int brow = tid >> 5, bcol = (tid & 31) * 4;
    const float* arowptr = (rbase + arow < M) ? A + (long long)(rbase + arow) * K : nullptr;

    for (int kt = 0; kt < K; kt += BK) {
        float4 av = make_float4(0.f, 0.f, 0.f, 0.f);
        if (arowptr) {
            int kc = kt + acol;
            if (kc + 3 < K) av = *(const float4*)(arowptr + kc);
            else {
                if (kc + 0 < K) av.x = arowptr[kc + 0];
                if (kc + 1 < K) av.y = arowptr[kc + 1];
                if (kc + 2 < K) av.z = arowptr[kc + 2];
                if (kc + 3 < K) av.w = arowptr[kc + 3];
            }
        }
        As[acol + 0][arow] = av.x; As[acol + 1][arow] = av.y;
        As[acol + 2][arow] = av.z; As[acol + 3][arow] = av.w;
        float4 bv = make_float4(0.f, 0.f, 0.f, 0.f);
        {
            int kr = kt + brow, cc = cbase + bcol;
            if (kr < K) {
                const float* bp = B + (long long)kr * N + cc;
                if (cc + 3 < N) bv = *(const float4*)bp;
                else {
                    if (cc + 0 < N) bv.x = bp[0];
                    if (cc + 1 < N) bv.y = bp[1];
                    if (cc + 2 < N) bv.z = bp[2];
                    if (cc + 3 < N) bv.w = bp[3];
                }
            }
        }
        *(float4*)&Bs[brow][bcol] = bv;
        __syncthreads();
#pragma unroll
        for (int k = 0; k < BK; k++) {
            float ra[8], rb[8];
            *(float4*)&ra[0] = *(const float4*)&As[k][ty * 4];
            *(float4*)&ra[4] = *(const float4*)&As[k][64 + ty * 4];
            *(float4*)&rb[0] = *(const float4*)&Bs[k][tx * 4];
            *(float4*)&rb[4] = *(const float4*)&Bs[k][64 + tx * 4];
#pragma unroll
            for (int i = 0; i < 8; i++)
#pragma unroll
                for (int j = 0; j < 8; j++) acc[i][j] += ra[i] * rb[j];
        }
        __syncthreads();
    }
#pragma unroll
    for (int i = 0; i < 8; i++) {
        int r = rbase + ((i < 4) ? (ty * 4 + i) : (64 + ty * 4 + i - 4));
        if (r >= M) continue;
#pragma unroll
        for (int j = 0; j < 8; j++) {
            int c = cbase + ((j < 4) ? (tx * 4 + j) : (64 + tx * 4 + j - 4));
            if (c >= N) continue;
            float v = acc[i][j];
            if (EPI >= 1) v += bias[c];
            if (EPI == 1) v = fmaxf(v, 0.0f);
            if (OUTH) Ch[(long long)r * N + c] = __float2half_rn(v);
            else      C[(long long)r * N + c] = v;
        }
    }
}

// ---------------- skinny GEMM for gc4 ----------------
__global__ void skinny16_kernel(const float* __restrict__ X, const float* __restrict__ W,
                                float* __restrict__ C, int M)
{
    __shared__ float Ws[256 * 16];
    int tid = threadIdx.x;   // 128
    for (int i = tid; i < 256 * 16; i += 128) Ws[i] = W[i];
    __syncthreads();
    int r = blockIdx.x * 128 + tid;
    if (r >= M) return;
    const float* x = X + (long long)r * 256;
    float acc[16];
#pragma unroll
    for (int q = 0; q < 16; q++) acc[q] = 0.0f;
    for (int k = 0; k < 256; k += 4) {
        float4 a = *(const float4*)(x + k);
#pragma unroll
        for (int q = 0; q < 16; q++)
            acc[q] += a.x * Ws[(k + 0) * 16 + q] + a.y * Ws[(k + 1) * 16 + q]
                    + a.z * Ws[(k + 2) * 16 + q] + a.w * Ws[(k + 3) * 16 + q];
    }
    float* co = C + (long long)r * 16;
#pragma unroll
    for (int q = 0; q < 16; q += 4)
        *(float4*)(co + q) = make_float4(acc[q], acc[q + 1], acc[q + 2], acc[q + 3]);
}

// ---------------- misc ----------------
__global__ void degree_kernel(const float* __restrict__ z, const float* __restrict__ Wr,
                              const float* __restrict__ br, float* __restrict__ deg_out,
                              int* __restrict__ pdeg, int n)
{
    int r = blockIdx.x * (blockDim.x >> 5) + (threadIdx.x >> 5);
    int lane = threadIdx.x & 31;
    if (r >= n) return;
    float s = z[(long long)r * LAT + lane] * Wr[lane]
            + z[(long long)r * LAT + 32 + lane] * Wr[32 + lane];
#pragma unroll
    for (int o = 16; o; o >>= 1) s += __shfl_xor_sync(0xffffffffu, s, o);
    if (lane == 0) {
        float d = fmaxf(s + br[0], 0.0f);
        deg_out[r] = d;
        int pi = (int)d;
        if (pi > NPRED) pi = NPRED;
        pdeg[r] = pi;
    }
}

__global__ void add_kernel(float* __restrict__ o, const float* __restrict__ a,
                           const float* __restrict__ b, long long n)
{
    long long i = (long long)blockIdx.x * blockDim.x + threadIdx.x;
    if (i < n) o[i] = a[i] + b[i];
}

// ---------------- host ----------------
static inline int cdiv(long long a, long long b) { return (int)((a + b - 1) / b); }

extern "C" void kernel_launch(void* const* d_in, const int* in_sizes, int n_in,
                              void* d_out, int out_size)
{
    const float* feat     = (const float*)d_in[0];
    const void*  edges    = d_in[1];
    const void*  adj_rows = d_in[2];
    const void*  adj_cols = d_in[3];
    const float* adj_vals = (const float*)d_in[4];
    const float* noise    = (const float*)d_in[5];
    const float* W_gc1 = (const float*)d_in[6];   const float* b_gc1 = (const float*)d_in[7];
    const float* W_gc2 = (const float*)d_in[8];   const float* b_gc2 = (const float*)d_in[9];
    const float* W_reg = (const float*)d_in[10];  const float* b_reg = (const float*)d_in[11];
    const float* W_fc1 = (const float*)d_in[12];  const float* b_fc1 = (const float*)d_in[13];
    const float* W_fc2 = (const float*)d_in[14];  const float* b_fc2 = (const float*)d_in[15];
    const float* W_flat = (const float*)d_in[16]; const float* b_flat = (const float*)d_in[17];
    const float* W_gc3 = (const float*)d_in[18];  const float* b_gc3 = (const float*)d_in[19];
    const float* W_gc4 = (const float*)d_in[20];  const float* b_gc4 = (const float*)d_in[21];

    float* out = (float*)d_out;
    float* out_deg = out;
    float* out_gen = out + OUT_GEN_OFF;
    float* out_nc  = out + OUT_NC_OFF;

    const long long nnz_adj = in_sizes[2];
    const int E = in_sizes[1] / 2;

    void* p;
    float *bufA, *bufB, *z, *zn, *c7;
    __half *g1h, *g2h, *fillh, *wh_fc2, *wh_flat, *wh_gc3;
    int *pdeg, *cnt, *fill, *off_enc, *off_mend, *ecol, *mcol;
    float *eval;
    cudaGetSymbolAddress(&p, g_bufA);  bufA  = (float*)p;
    cudaGetSymbolAddress(&p, g_bufB);  bufB  = (float*)p;
    cudaGetSymbolAddress(&p, g_z);     z     = (float*)p;
    cudaGetSymbolAddress(&p, g_zn);    zn    = (float*)p;
    cudaGetSymbolAddress(&p, g_c7);    c7    = (float*)p;
    cudaGetSymbolAddress(&p, g_pdeg);  pdeg  = (int*)p;
    cudaGetSymbolAddress(&p, g_cnt);   cnt   = (int*)p;
    cudaGetSymbolAddress(&p, g_fill);  fill  = (int*)p;
    cudaGetSymbolAddress(&p, g_off_enc);  off_enc  = (int*)p;
    cudaGetSymbolAddress(&p, g_off_mend); off_mend = (int*)p;
    cudaGetSymbolAddress(&p, g_ecol);  ecol  = (int*)p;
    cudaGetSymbolAddress(&p, g_eval);  eval  = (float*)p;
    cudaGetSymbolAddress(&p, g_mcol);  mcol  = (int*)p;
    cudaGetSymbolAddress(&p, g_g1h);   g1h   = (__half*)p;
    cudaGetSymbolAddress(&p, g_g2h);   g2h   = (__half*)p;
    cudaGetSymbolAddress(&p, g_fillh); fillh = (__half*)p;
    cudaGetSymbolAddress(&p, g_wh_fc2);  wh_fc2  = (__half*)p;
    cudaGetSymbolAddress(&p, g_wh_flat); wh_flat = (__half*)p;
    cudaGetSymbolAddress(&p, g_wh_gc3);  wh_gc3  = (__half*)p;

    cudaFuncSetAttribute((const void*)hmma_gemm_kernel<1, 1>,
                         cudaFuncAttributeMaxDynamicSharedMemorySize, H_SMEM_TOTAL);
    cudaFuncSetAttribute((const void*)hmma_gemm_kernel<2, 2>,
                         cudaFuncAttributeMaxDynamicSharedMemorySize, H_SMEM_TOTAL);
    cudaFuncSetAttribute((const void*)hmma_gemm_kernel<0, 0>,
                         cudaFuncAttributeMaxDynamicSharedMemorySize, H_SMEM_TOTAL);

    const int TB = 256;
    dim3 tblk(32, 8);

    // 0) index-width detection + weight transposes (fp16, K-major) + feat->fillh
    detect_idx_kernel<<<1, 32>>>(adj_rows);
    transpose_half_kernel<<<dim3(cdiv(256, 32), cdiv(2048, 32)), tblk>>>(W_fc2, wh_fc2, 256, 2048, 256, 2048);
    transpose_half_kernel<<<dim3(cdiv(2048, 32), cdiv(2560, 32)), tblk>>>(W_flat, wh_flat, 2048, 2500, 2048, 2560);
    transpose_half_kernel<<<dim3(cdiv(512, 32), cdiv(256, 32)), tblk>>>(W_gc3, wh_gc3, 500, 256, 512, 256);
    feat_to_fillh_kernel<<<cdiv((long long)NNODES * 512, TB), TB>>>(feat, fillh);

    // 0b) encoder CSR build
    cudaMemsetAsync(cnt, 0, NNODES * sizeof(int));
    enc_hist_kernel<<<cdiv(nnz_adj, TB), TB>>>(adj_rows, nnz_adj);
    scan_kernel<<<1, 1024>>>(cnt, off_enc, fill, NNODES);
    enc_fill_kernel<<<cdiv(nnz_adj, TB), TB>>>(adj_rows, adj_cols, adj_vals, nnz_adj);

    // 1) XW1 = feat @ W_gc1 (fp32 exact — feeds the int(degree) cliff)
    {
        dim3 grid(cdiv(HID, BN), cdiv(NNODES, BM));
        sgemm_kernel<0, false><<<grid, TB>>>(feat, W_gc1, nullptr, bufA, nullptr, NNODES, HID, FEAT);
    }
    // 2) h = relu(spmm + b1) — CSR gather
    spmm_gather_kernel<256, false><<<cdiv(NNODES, 8), TB>>>(off_enc, ecol, eval, bufA, b_gc1, bufB, NNODES);
    // 3) hW2 = h @ W_gc2
    {
        dim3 grid(cdiv(LAT, BN), cdiv(NNODES, BM));
        sgemm_kernel<0, false><<<grid, TB>>>(bufB, W_gc2, nullptr, bufA, nullptr, NNODES, LAT, HID);
    }
    // 4) z = relu(spmm + b2)
    spmm_gather_kernel<64, false><<<cdiv(NNODES, 8), TB>>>(off_enc, ecol, eval, bufA, b_gc2, z, NNODES);
    // 5) degree + pred_deg
    degree_kernel<<<cdiv(NNODES, TB / 32), TB>>>(z, W_reg, b_reg, out_deg, pdeg, NNODES);
    // 5b) mend CSR build
    cudaMemsetAsync(cnt, 0, NODE_LEN * sizeof(int));
    mend_hist_edges_kernel<<<cdiv(E, TB), TB>>>(edges, E);
    mend_hist_new_kernel<<<cdiv(NNODES * NPRED, TB), TB>>>(pdeg);
    scan_kernel<<<1, 1024>>>(cnt, off_mend, fill, NODE_LEN);
    mend_fill_edges_kernel<<<cdiv(E, TB), TB>>>(edges, E);
    mend_fill_new_kernel<<<cdiv(NNODES * NPRED, TB), TB>>>(pdeg);
    // 6) zn = z + noise
    add_kernel<<<cdiv((long long)NNODES * LAT, TB), TB>>>(zn, z, noise, (long long)NNODES * LAT);
    // 7) g1h = half(relu(zn @ W_fc1 + b)) — SIMT, half output
    {
        dim3 grid(cdiv(FC1N, BN), cdiv(NNODES, BM));
        sgemm_kernel<1, true><<<grid, TB>>>(zn, W_fc1, b_fc1, nullptr, g1h, NNODES, FC1N, LAT);
    }
    // 8) g2h = half(relu(g1h @ W_fc2 + b)) — fp16 mma
    {
        dim3 grid(FC2N / 128, cdiv(NNODES, 128));
        hmma_gemm_kernel<1, 1><<<grid, 256, H_SMEM_TOTAL>>>(
            g1h, wh_fc2, b_fc2, nullptr, g2h, NNODES, FC2N, FC1N, 256);
    }
    // 9) gen_feat = tanh(g2h @ W_flat + b) — fp16 mma; writes f32 out_gen + half fillh gen rows
    {
        dim3 grid(2560 / 128, cdiv(NNODES, 128));
        hmma_gemm_kernel<2, 2><<<grid, 256, H_SMEM_TOTAL>>>(
            g2h, wh_flat, b_flat, out_gen, fillh, NNODES, GENF, FC2N, 2048);
    }
    // 10) fillW3 = fillh @ W_gc3 — fp16 mma (K padded to 512)
    {
        dim3 grid(HID / 128, cdiv(NODE_LEN, 128));
        hmma_gemm_kernel<0, 0><<<grid, 256, H_SMEM_TOTAL>>>(
            fillh, wh_gc3, nullptr, bufA, nullptr, NODE_LEN, HID, 512, 512);
    }
    // 12) mend layer 1 — CSR gather, fused normalize+bias+relu
    spmm_gather_kernel<256, true><<<cdiv(NODE_LEN, 8), TB>>>(off_mend, mcol, nullptr, bufA, b_gc3, bufB, NODE_LEN);
    // 13) c7 = h2 @ W_gc4 — skinny N=16
    skinny16_kernel<<<cdiv(NODE_LEN, 128), 128>>>(bufB, W_gc4, c7, NODE_LEN);
    // 14) mend layer 2 — CSR gather
    spmm_gather_kernel<16, true><<<cdiv(NODE_LEN, 8), TB>>>(off_mend, mcol, nullptr, c7, b_gc4, out_nc, NODE_LEN);

    (void)n_in; (void)out_size;
}